// round 1
// baseline (speedup 1.0000x reference)
#include <cuda_runtime.h>

// ---------------------------------------------------------------------------
// EncoderBlock: pre-norm transformer block, fp32 baseline
// B=2, S=2048, D=1024, H=16, DK=64, DFF=4096
// ---------------------------------------------------------------------------

namespace {
constexpr int B_ = 2, S_ = 2048, D_ = 1024, H_ = 16, DK_ = 64, DFF_ = 4096;
constexpr int ROWS_ = B_ * S_;            // 4096
constexpr float EPS_ = 1e-6f;
}

// Scratch buffers (allocation-free: __device__ globals)
__device__ float g_ln[ROWS_ * D_];
__device__ float g_q[ROWS_ * D_];
__device__ float g_k[ROWS_ * D_];
__device__ float g_v[ROWS_ * D_];
__device__ float g_attn[ROWS_ * D_];
__device__ float g_x2[ROWS_ * D_];
__device__ float g_hbuf[ROWS_ * DFF_];
__device__ float g_scores[(size_t)B_ * H_ * S_ * S_];   // 512 MB

// ---------------------------------------------------------------------------
// LayerNorm: custom variant — unbiased std (ddof=1), scalar alpha/beta,
// y = alpha*(x-mean)/(std+eps)+beta.  One block per row (D=1024), 256 thr.
// ---------------------------------------------------------------------------
__global__ void layernorm_kernel(const float* __restrict__ x, float* __restrict__ y,
                                 const float* __restrict__ alpha,
                                 const float* __restrict__ beta) {
    __shared__ float red_s[256];
    __shared__ float red_q[256];
    const int tid = threadIdx.x;
    const size_t off = (size_t)blockIdx.x * D_;
    float4 r = reinterpret_cast<const float4*>(x + off)[tid];
    float s = r.x + r.y + r.z + r.w;
    float q = r.x * r.x + r.y * r.y + r.z * r.z + r.w * r.w;
    red_s[tid] = s;
    red_q[tid] = q;
    __syncthreads();
    #pragma unroll
    for (int st = 128; st > 0; st >>= 1) {
        if (tid < st) {
            red_s[tid] += red_s[tid + st];
            red_q[tid] += red_q[tid + st];
        }
        __syncthreads();
    }
    const float mean = red_s[0] * (1.0f / D_);
    float var = (red_q[0] - (float)D_ * mean * mean) * (1.0f / (float)(D_ - 1));
    var = fmaxf(var, 0.0f);
    const float sc = alpha[0] / (sqrtf(var) + EPS_);
    const float sh = beta[0];
    float4 o;
    o.x = (r.x - mean) * sc + sh;
    o.y = (r.y - mean) * sc + sh;
    o.z = (r.z - mean) * sc + sh;
    o.w = (r.w - mean) * sc + sh;
    reinterpret_cast<float4*>(y + off)[tid] = o;
}

// ---------------------------------------------------------------------------
// Generic tiled GEMM.
//   C[m,n] = scale * sum_k A[m,k] * B(n,k) (BNT=true, "NT": B is [N,K])
//                          or       B(k,n) (BNT=false, "NN": B is [K,N])
//   (+ bias[n]) (+ ReLU) (+ res[m,n], same layout as C)
// Two-level batching: z -> (zb, zh) = (z/batH, z%batH), per-operand strides.
// All problem dims are exact multiples of the tiles -> no bounds checks.
// ---------------------------------------------------------------------------
template <int BM, int BN, int BK, int TM, int TN, bool BNT, bool RELU>
__global__ void __launch_bounds__(256, 2)
gemm_kernel(const float* __restrict__ A, const float* __restrict__ Bm,
            const float* __restrict__ bias, const float* __restrict__ res,
            float* __restrict__ C,
            int K, int lda, int ldb, int ldc,
            int batH,
            long long sAb, long long sAh,
            long long sBb, long long sBh,
            long long sCb, long long sCh,
            float scale) {
    constexpr int NTX = BN / TN;
    constexpr int NTY = BM / TM;
    static_assert(NTX * NTY == 256, "thread layout");
    constexpr int ALD = BM * BK / 256;
    constexpr int BLD = BN * BK / 256;

    __shared__ float As[BK][BM + 4];
    __shared__ float Bs[BK][BN + 4];

    const int z = blockIdx.z;
    const int zb = z / batH;
    const int zh = z % batH;
    A  += zb * sAb + zh * sAh;
    Bm += zb * sBb + zh * sBh;
    const long long coff = zb * sCb + zh * sCh;
    C += coff;
    if (res) res += coff;

    const int tid = threadIdx.x;
    const int tx = tid % NTX;
    const int ty = tid / NTX;
    const int row0 = blockIdx.y * BM;
    const int col0 = blockIdx.x * BN;

    float acc[TM][TN];
    #pragma unroll
    for (int i = 0; i < TM; i++)
        #pragma unroll
        for (int j = 0; j < TN; j++) acc[i][j] = 0.0f;

    for (int k0 = 0; k0 < K; k0 += BK) {
        #pragma unroll
        for (int l = 0; l < ALD; l++) {
            const int idx = tid + l * 256;
            const int m = idx / BK;
            const int kk = idx % BK;
            As[kk][m] = A[(long long)(row0 + m) * lda + (k0 + kk)];
        }
        #pragma unroll
        for (int l = 0; l < BLD; l++) {
            const int idx = tid + l * 256;
            if (BNT) {
                const int n = idx / BK;
                const int kk = idx % BK;
                Bs[kk][n] = Bm[(long long)(col0 + n) * ldb + (k0 + kk)];
            } else {
                const int kk = idx / BN;
                const int n = idx % BN;
                Bs[kk][n] = Bm[(long long)(k0 + kk) * ldb + (col0 + n)];
            }
        }
        __syncthreads();
        #pragma unroll
        for (int kk = 0; kk < BK; kk++) {
            float a[TM], b[TN];
            #pragma unroll
            for (int c = 0; c < TM / 4; c++) {
                float4 t = *reinterpret_cast<const float4*>(&As[kk][ty * TM + c * 4]);
                a[c * 4 + 0] = t.x; a[c * 4 + 1] = t.y;
                a[c * 4 + 2] = t.z; a[c * 4 + 3] = t.w;
            }
            #pragma unroll
            for (int c = 0; c < TN / 4; c++) {
                float4 t = *reinterpret_cast<const float4*>(&Bs[kk][tx * TN + c * 4]);
                b[c * 4 + 0] = t.x; b[c * 4 + 1] = t.y;
                b[c * 4 + 2] = t.z; b[c * 4 + 3] = t.w;
            }
            #pragma unroll
            for (int i = 0; i < TM; i++)
                #pragma unroll
                for (int j = 0; j < TN; j++)
                    acc[i][j] = fmaf(a[i], b[j], acc[i][j]);
        }
        __syncthreads();
    }

    #pragma unroll
    for (int i = 0; i < TM; i++) {
        const long long m = row0 + ty * TM + i;
        #pragma unroll
        for (int c = 0; c < TN / 4; c++) {
            const int n = col0 + tx * TN + c * 4;
            float4 v;
            v.x = acc[i][c * 4 + 0] * scale;
            v.y = acc[i][c * 4 + 1] * scale;
            v.z = acc[i][c * 4 + 2] * scale;
            v.w = acc[i][c * 4 + 3] * scale;
            if (bias) {
                float4 bv = *reinterpret_cast<const float4*>(&bias[n]);
                v.x += bv.x; v.y += bv.y; v.z += bv.z; v.w += bv.w;
            }
            if (RELU) {
                v.x = fmaxf(v.x, 0.0f); v.y = fmaxf(v.y, 0.0f);
                v.z = fmaxf(v.z, 0.0f); v.w = fmaxf(v.w, 0.0f);
            }
            if (res) {
                float4 rv = *reinterpret_cast<const float4*>(&res[m * ldc + n]);
                v.x += rv.x; v.y += rv.y; v.z += rv.z; v.w += rv.w;
            }
            *reinterpret_cast<float4*>(&C[m * ldc + n]) = v;
        }
    }
}

// ---------------------------------------------------------------------------
// Masked softmax over the last axis of scores[B*H, S, S].
// mask[b, k]: where mask==0 -> value replaced with -1e9 before softmax.
// One block (256 thr) per (z, q-row); row kept in registers (8 elems/thread).
// ---------------------------------------------------------------------------
__global__ void softmax_kernel(float* __restrict__ scores, const int* __restrict__ mask) {
    const int z = blockIdx.y;          // b*H + h
    const int b = z / H_;
    float* row = scores + (long long)z * S_ * S_ + (long long)blockIdx.x * S_;
    const int* mrow = mask + b * S_;
    const int tid = threadIdx.x;

    float r[8];
    float lmax = -3.4e38f;
    #pragma unroll
    for (int j = 0; j < 8; j++) {
        const int kk = tid + j * 256;
        float v = row[kk];
        if (mrow[kk] == 0) v = -1e9f;
        r[j] = v;
        lmax = fmaxf(lmax, v);
    }

    __shared__ float red[256];
    red[tid] = lmax;
    __syncthreads();
    #pragma unroll
    for (int st = 128; st > 0; st >>= 1) {
        if (tid < st) red[tid] = fmaxf(red[tid], red[tid + st]);
        __syncthreads();
    }
    const float m = red[0];
    __syncthreads();

    float lsum = 0.0f;
    #pragma unroll
    for (int j = 0; j < 8; j++) {
        r[j] = __expf(r[j] - m);
        lsum += r[j];
    }
    red[tid] = lsum;
    __syncthreads();
    #pragma unroll
    for (int st = 128; st > 0; st >>= 1) {
        if (tid < st) red[tid] += red[tid + st];
        __syncthreads();
    }
    const float inv = 1.0f / red[0];
    #pragma unroll
    for (int j = 0; j < 8; j++) row[tid + j * 256] = r[j] * inv;
}

// ---------------------------------------------------------------------------
// kernel_launch
// ---------------------------------------------------------------------------
extern "C" void kernel_launch(void* const* d_in, const int* in_sizes, int n_in,
                              void* d_out, int out_size) {
    const float* x    = (const float*)d_in[0];
    const int*   msk  = (const int*)  d_in[1];
    const float* wq   = (const float*)d_in[2];
    const float* bq   = (const float*)d_in[3];
    const float* wk   = (const float*)d_in[4];
    const float* bk_  = (const float*)d_in[5];
    const float* wv   = (const float*)d_in[6];
    const float* bv   = (const float*)d_in[7];
    const float* wo   = (const float*)d_in[8];
    const float* bo   = (const float*)d_in[9];
    const float* w1   = (const float*)d_in[10];
    const float* b1   = (const float*)d_in[11];
    const float* w2   = (const float*)d_in[12];
    const float* b2   = (const float*)d_in[13];
    const float* a1   = (const float*)d_in[14];
    const float* be1  = (const float*)d_in[15];
    const float* a2   = (const float*)d_in[16];
    const float* be2  = (const float*)d_in[17];
    float* out = (float*)d_out;

    float *ln, *q, *kb, *v, *attn, *x2, *hb, *sc;
    cudaGetSymbolAddress((void**)&ln,   g_ln);
    cudaGetSymbolAddress((void**)&q,    g_q);
    cudaGetSymbolAddress((void**)&kb,   g_k);
    cudaGetSymbolAddress((void**)&v,    g_v);
    cudaGetSymbolAddress((void**)&attn, g_attn);
    cudaGetSymbolAddress((void**)&x2,   g_x2);
    cudaGetSymbolAddress((void**)&hb,   g_hbuf);
    cudaGetSymbolAddress((void**)&sc,   g_scores);

    const long long sSD = (long long)S_ * D_;       // per-batch stride in q/k/v
    const long long sSS = (long long)S_ * S_;       // per-head stride in scores
    const long long sHSS = (long long)H_ * sSS;     // per-batch stride in scores

    // 1. LN1
    layernorm_kernel<<<ROWS_, 256>>>(x, ln, a1, be1);

    // 2-4. Q, K, V projections: [4096,1024] = ln @ W^T + b   (NT)
    gemm_kernel<128, 128, 16, 8, 8, true, false>
        <<<dim3(D_ / 128, ROWS_ / 128, 1), 256>>>(
            ln, wq, bq, nullptr, q, D_, D_, D_, D_,
            1, 0, 0, 0, 0, 0, 0, 1.0f);
    gemm_kernel<128, 128, 16, 8, 8, true, false>
        <<<dim3(D_ / 128, ROWS_ / 128, 1), 256>>>(
            ln, wk, bk_, nullptr, kb, D_, D_, D_, D_,
            1, 0, 0, 0, 0, 0, 0, 1.0f);
    gemm_kernel<128, 128, 16, 8, 8, true, false>
        <<<dim3(D_ / 128, ROWS_ / 128, 1), 256>>>(
            ln, wv, bv, nullptr, v, D_, D_, D_, D_,
            1, 0, 0, 0, 0, 0, 0, 1.0f);

    // 5. scores[z,q,k] = (Q_bh @ K_bh^T) / 8   (batched NT, K=64)
    gemm_kernel<128, 128, 16, 8, 8, true, false>
        <<<dim3(S_ / 128, S_ / 128, B_ * H_), 256>>>(
            q, kb, nullptr, nullptr, sc, DK_, D_, D_, S_,
            H_, sSD, (long long)DK_, sSD, (long long)DK_,
            sHSS, sSS, 0.125f);

    // 6. masked softmax
    softmax_kernel<<<dim3(S_, B_ * H_), 256>>>(sc, msk);

    // 7. attn = P @ V   (batched NN, N=64, K=2048)
    gemm_kernel<128, 64, 16, 8, 4, false, false>
        <<<dim3(1, S_ / 128, B_ * H_), 256>>>(
            sc, v, nullptr, nullptr, attn, S_, S_, D_, D_,
            H_, sHSS, sSS, sSD, (long long)DK_,
            sSD, (long long)DK_, 1.0f);

    // 8. x2 = attn @ wo^T + bo + x   (NT + residual)
    gemm_kernel<128, 128, 16, 8, 8, true, false>
        <<<dim3(D_ / 128, ROWS_ / 128, 1), 256>>>(
            attn, wo, bo, x, x2, D_, D_, D_, D_,
            1, 0, 0, 0, 0, 0, 0, 1.0f);

    // 9. LN2
    layernorm_kernel<<<ROWS_, 256>>>(x2, ln, a2, be2);

    // 10. h = relu(ln @ w1^T + b1)   [4096, 4096]
    gemm_kernel<128, 128, 16, 8, 8, true, true>
        <<<dim3(DFF_ / 128, ROWS_ / 128, 1), 256>>>(
            ln, w1, b1, nullptr, hb, D_, D_, D_, DFF_,
            1, 0, 0, 0, 0, 0, 0, 1.0f);

    // 11. out = h @ w2^T + b2 + x2   [4096, 1024]
    gemm_kernel<128, 128, 16, 8, 8, true, false>
        <<<dim3(D_ / 128, ROWS_ / 128, 1), 256>>>(
            hb, w2, b2, x2, out, DFF_, DFF_, DFF_, D_,
            1, 0, 0, 0, 0, 0, 0, 1.0f);
}

// round 3
// speedup vs baseline: 2.9929x; 2.9929x over previous
#include <cuda_runtime.h>
#include <cstdint>

// ---------------------------------------------------------------------------
// EncoderBlock: pre-norm transformer block.
// GEMMs via mma.sync m16n8k8 tf32 (tensor cores, base sm_103-compatible PTX).
// B=2, S=2048, D=1024, H=16, DK=64, DFF=4096
// ---------------------------------------------------------------------------

namespace {
constexpr int B_ = 2, S_ = 2048, D_ = 1024, H_ = 16, DK_ = 64, DFF_ = 4096;
constexpr int ROWS_ = B_ * S_;            // 4096
constexpr float EPS_ = 1e-6f;
}

// Scratch (allocation-free: __device__ globals)
__device__ __align__(16) float g_ln[ROWS_ * D_];
__device__ __align__(16) float g_q[ROWS_ * D_];
__device__ __align__(16) float g_k[ROWS_ * D_];
__device__ __align__(16) float g_v[ROWS_ * D_];
__device__ __align__(16) float g_vT[B_ * H_ * DK_ * S_];
__device__ __align__(16) float g_attn[ROWS_ * D_];
__device__ __align__(16) float g_x2[ROWS_ * D_];
__device__ __align__(16) float g_hbuf[ROWS_ * DFF_];
__device__ __align__(16) float g_scores[(size_t)B_ * H_ * S_ * S_];   // 512 MB

// ---------------------------------------------------------------------------
// PTX helpers
// ---------------------------------------------------------------------------
__device__ __forceinline__ uint32_t smem_u32(const void* p) {
    uint32_t a;
    asm("{ .reg .u64 t; cvta.to.shared.u64 t, %1; cvt.u32.u64 %0, t; }"
        : "=r"(a) : "l"(p));
    return a;
}

__device__ __forceinline__ void cp_async16(uint32_t s, const void* g) {
    asm volatile("cp.async.cg.shared.global [%0], [%1], 16;" :: "r"(s), "l"(g));
}
#define CP_COMMIT() asm volatile("cp.async.commit_group;" ::: "memory")
#define CP_WAIT(n)  asm volatile("cp.async.wait_group %0;" :: "n"(n) : "memory")

__device__ __forceinline__ uint32_t f2tf32(float f) {
    uint32_t u;
    asm("cvt.rna.tf32.f32 %0, %1;" : "=r"(u) : "f"(f));
    return u;
}

__device__ __forceinline__ void mma_tf32(float* c, const uint32_t* a, const uint32_t* b) {
    asm volatile(
        "mma.sync.aligned.m16n8k8.row.col.f32.tf32.tf32.f32 "
        "{%0,%1,%2,%3}, {%4,%5,%6,%7}, {%8,%9}, {%0,%1,%2,%3};"
        : "+f"(c[0]), "+f"(c[1]), "+f"(c[2]), "+f"(c[3])
        : "r"(a[0]), "r"(a[1]), "r"(a[2]), "r"(a[3]), "r"(b[0]), "r"(b[1]));
}

// ---------------------------------------------------------------------------
// LayerNorm (exact fp32): unbiased std (ddof=1), scalar alpha/beta
// ---------------------------------------------------------------------------
__global__ void layernorm_kernel(const float* __restrict__ x, float* __restrict__ y,
                                 const float* __restrict__ alpha,
                                 const float* __restrict__ beta) {
    __shared__ float red_s[256];
    __shared__ float red_q[256];
    const int tid = threadIdx.x;
    const size_t off = (size_t)blockIdx.x * D_;
    float4 r = reinterpret_cast<const float4*>(x + off)[tid];
    float s = r.x + r.y + r.z + r.w;
    float q = r.x * r.x + r.y * r.y + r.z * r.z + r.w * r.w;
    red_s[tid] = s;
    red_q[tid] = q;
    __syncthreads();
    #pragma unroll
    for (int st = 128; st > 0; st >>= 1) {
        if (tid < st) { red_s[tid] += red_s[tid + st]; red_q[tid] += red_q[tid + st]; }
        __syncthreads();
    }
    const float mean = red_s[0] * (1.0f / D_);
    float var = (red_q[0] - (float)D_ * mean * mean) * (1.0f / (float)(D_ - 1));
    var = fmaxf(var, 0.0f);
    const float sc = alpha[0] / (sqrtf(var) + EPS_);
    const float sh = beta[0];
    float4 o;
    o.x = (r.x - mean) * sc + sh;
    o.y = (r.y - mean) * sc + sh;
    o.z = (r.z - mean) * sc + sh;
    o.w = (r.w - mean) * sc + sh;
    reinterpret_cast<float4*>(y + off)[tid] = o;
}

// ---------------------------------------------------------------------------
// V transpose: vT[(b*H+h)][n][s] = v[b][s][h*DK+n]
// ---------------------------------------------------------------------------
__global__ void transpose_v_kernel(const float* __restrict__ v, float* __restrict__ vT) {
    __shared__ float t[32][33];
    const int bh = blockIdx.z;
    const int b = bh / H_, h = bh % H_;
    const int s0 = blockIdx.x * 32, n0 = blockIdx.y * 32;
    const int tx = threadIdx.x, ty = threadIdx.y;   // 32 x 8
    const float* src = v + ((long long)b * S_ + s0) * D_ + h * DK_ + n0;
    #pragma unroll
    for (int i = 0; i < 32; i += 8)
        t[ty + i][tx] = src[(long long)(ty + i) * D_ + tx];
    __syncthreads();
    float* dst = vT + ((long long)bh * DK_ + n0) * S_ + s0;
    #pragma unroll
    for (int i = 0; i < 32; i += 8)
        dst[(long long)(ty + i) * S_ + tx] = t[tx][ty + i];
}

// ---------------------------------------------------------------------------
// Masked softmax over last axis of scores[B*H, S, S]
// ---------------------------------------------------------------------------
__global__ void softmax_kernel(float* __restrict__ scores, const int* __restrict__ mask) {
    const int z = blockIdx.y;
    const int b = z / H_;
    float* row = scores + (long long)z * S_ * S_ + (long long)blockIdx.x * S_;
    const int* mrow = mask + b * S_;
    const int tid = threadIdx.x;

    float r[8];
    float lmax = -3.4e38f;
    #pragma unroll
    for (int j = 0; j < 8; j++) {
        const int kk = tid + j * 256;
        float v = row[kk];
        if (mrow[kk] == 0) v = -1e9f;
        r[j] = v;
        lmax = fmaxf(lmax, v);
    }
    __shared__ float red[256];
    red[tid] = lmax;
    __syncthreads();
    #pragma unroll
    for (int st = 128; st > 0; st >>= 1) {
        if (tid < st) red[tid] = fmaxf(red[tid], red[tid + st]);
        __syncthreads();
    }
    const float m = red[0];
    __syncthreads();
    float lsum = 0.0f;
    #pragma unroll
    for (int j = 0; j < 8; j++) { r[j] = __expf(r[j] - m); lsum += r[j]; }
    red[tid] = lsum;
    __syncthreads();
    #pragma unroll
    for (int st = 128; st > 0; st >>= 1) {
        if (tid < st) red[tid] += red[tid + st];
        __syncthreads();
    }
    const float inv = 1.0f / red[0];
    #pragma unroll
    for (int j = 0; j < 8; j++) row[tid + j * 256] = r[j] * inv;
}

// ---------------------------------------------------------------------------
// tf32 tensor-core GEMM (NT): C[m,n] = scale*sum_k A[m,k]*B[n,k] (+bias)(+relu)(+res)
// Block 128(M) x BN(N) x 32(K). 256 threads = 8 warps (2x4), warp tile 64 x BN/4.
// 3-stage cp.async pipeline. SMEM 16B-chunk XOR swizzle (ch ^= row&7).
// ---------------------------------------------------------------------------
template <int BN, bool RELU>
__global__ void __launch_bounds__(256, 2)
mma_gemm(const float* __restrict__ A, const float* __restrict__ Bm,
         const float* __restrict__ bias, const float* __restrict__ res,
         float* __restrict__ C,
         int K, int lda, int ldb, int ldc, int batH,
         long long sAb, long long sAh, long long sBb, long long sBh,
         long long sCb, long long sCh, float scale) {
    constexpr int NAt = BN / 32;            // N-atoms per warp (4 or 2)
    constexpr int NB4 = BN * 8 / 256;       // B float4 loads per thread (4 or 2)
    constexpr int STGF = (128 + BN) * 32;   // floats per stage
    constexpr int BOFF = 128 * 32;          // B region offset within stage (floats)

    extern __shared__ float sm[];

    const int tid = threadIdx.x;
    const int wid = tid >> 5;
    const int lane = tid & 31;
    const int grp = lane >> 2;              // 0..7
    const int tid4 = lane & 3;              // 0..3
    const int wr = wid >> 2;                // 0..1  (M)
    const int wc = wid & 3;                 // 0..3  (N)
    const int wm0 = wr * 64;
    const int wn0 = wc * (BN / 4);

    // batch offsets
    const int z = blockIdx.z;
    const int zb = z / batH, zh = z % batH;
    A  += zb * sAb + zh * sAh;
    Bm += zb * sBb + zh * sBh;
    const long long coff = zb * sCb + zh * sCh;
    C += coff;
    if (res) res += coff;

    const int row0 = blockIdx.y * 128;
    const int col0 = blockIdx.x * BN;

    // per-thread staging descriptors (16B chunks, XOR-swizzled)
    int aGo[4]; uint32_t aSm[4];
    #pragma unroll
    for (int l = 0; l < 4; l++) {
        const int idx4 = tid + l * 256;
        const int r = idx4 >> 3, ch = idx4 & 7;
        aGo[l] = (row0 + r) * lda + ch * 4;
        aSm[l] = (uint32_t)(r * 32 + ((ch ^ (r & 7)) << 2)) * 4u;
    }
    int bGo[NB4]; uint32_t bSm[NB4];
    #pragma unroll
    for (int l = 0; l < NB4; l++) {
        const int idx4 = tid + l * 256;
        const int r = idx4 >> 3, ch = idx4 & 7;
        bGo[l] = (col0 + r) * ldb + ch * 4;
        bSm[l] = (uint32_t)(BOFF + r * 32 + ((ch ^ (r & 7)) << 2)) * 4u;
    }
    const uint32_t smBase = smem_u32(sm);

    float acc[4][NAt][4];
    #pragma unroll
    for (int i = 0; i < 4; i++)
        #pragma unroll
        for (int j = 0; j < NAt; j++)
            #pragma unroll
            for (int e = 0; e < 4; e++) acc[i][j][e] = 0.0f;

    const int nch = K / 32;

    // prologue: stages 0, 1
    #pragma unroll
    for (int s = 0; s < 2; s++) {
        const uint32_t sb = smBase + (uint32_t)(s % 3) * STGF * 4u;
        const int k0 = s * 32;
        #pragma unroll
        for (int l = 0; l < 4; l++) cp_async16(sb + aSm[l], A + aGo[l] + k0);
        #pragma unroll
        for (int l = 0; l < NB4; l++) cp_async16(sb + bSm[l], Bm + bGo[l] + k0);
        CP_COMMIT();
    }

    for (int ci = 0; ci < nch; ci++) {
        if (ci + 2 < nch) { CP_WAIT(1); } else { CP_WAIT(0); }
        __syncthreads();
        if (ci + 2 < nch) {
            const int s = ci + 2;
            const uint32_t sb = smBase + (uint32_t)(s % 3) * STGF * 4u;
            const int k0 = s * 32;
            #pragma unroll
            for (int l = 0; l < 4; l++) cp_async16(sb + aSm[l], A + aGo[l] + k0);
            #pragma unroll
            for (int l = 0; l < NB4; l++) cp_async16(sb + bSm[l], Bm + bGo[l] + k0);
            CP_COMMIT();
        }

        const float* Abuf = sm + (ci % 3) * STGF;
        const float* Bbuf = Abuf + BOFF;

        #pragma unroll
        for (int ks = 0; ks < 4; ks++) {
            const int ce = ((ks * 2) ^ grp) << 2;       // even chunk, swizzled
            const int co = ((ks * 2 + 1) ^ grp) << 2;   // odd chunk, swizzled
            uint32_t a[4][4];
            #pragma unroll
            for (int ma = 0; ma < 4; ma++) {
                const int r0 = (wm0 + ma * 16 + grp) * 32;
                a[ma][0] = f2tf32(Abuf[r0 + ce + tid4]);
                a[ma][1] = f2tf32(Abuf[r0 + 256 + ce + tid4]);
                a[ma][2] = f2tf32(Abuf[r0 + co + tid4]);
                a[ma][3] = f2tf32(Abuf[r0 + 256 + co + tid4]);
            }
            uint32_t b[NAt][2];
            #pragma unroll
            for (int na = 0; na < NAt; na++) {
                const int n0 = (wn0 + na * 8 + grp) * 32;
                b[na][0] = f2tf32(Bbuf[n0 + ce + tid4]);
                b[na][1] = f2tf32(Bbuf[n0 + co + tid4]);
            }
            #pragma unroll
            for (int ma = 0; ma < 4; ma++)
                #pragma unroll
                for (int na = 0; na < NAt; na++)
                    mma_tf32(acc[ma][na], a[ma], b[na]);
        }
    }

    // epilogue: straight from accumulators (float2 granularity)
    #pragma unroll
    for (int ma = 0; ma < 4; ma++) {
        const int rr = row0 + wm0 + ma * 16 + grp;
        #pragma unroll
        for (int na = 0; na < NAt; na++) {
            const int cc = col0 + wn0 + na * 8 + tid4 * 2;
            float2 v0, v1;
            v0.x = acc[ma][na][0] * scale; v0.y = acc[ma][na][1] * scale;
            v1.x = acc[ma][na][2] * scale; v1.y = acc[ma][na][3] * scale;
            if (bias) {
                const float2 bv = *reinterpret_cast<const float2*>(bias + cc);
                v0.x += bv.x; v0.y += bv.y; v1.x += bv.x; v1.y += bv.y;
            }
            if (RELU) {
                v0.x = fmaxf(v0.x, 0.0f); v0.y = fmaxf(v0.y, 0.0f);
                v1.x = fmaxf(v1.x, 0.0f); v1.y = fmaxf(v1.y, 0.0f);
            }
            const long long o0 = (long long)rr * ldc + cc;
            const long long o1 = (long long)(rr + 8) * ldc + cc;
            if (res) {
                const float2 r0 = *reinterpret_cast<const float2*>(res + o0);
                const float2 r1 = *reinterpret_cast<const float2*>(res + o1);
                v0.x += r0.x; v0.y += r0.y; v1.x += r1.x; v1.y += r1.y;
            }
            *reinterpret_cast<float2*>(C + o0) = v0;
            *reinterpret_cast<float2*>(C + o1) = v1;
        }
    }
}

// ---------------------------------------------------------------------------
// kernel_launch
// ---------------------------------------------------------------------------
extern "C" void kernel_launch(void* const* d_in, const int* in_sizes, int n_in,
                              void* d_out, int out_size) {
    const float* x    = (const float*)d_in[0];
    const int*   msk  = (const int*)  d_in[1];
    const float* wq   = (const float*)d_in[2];
    const float* bq   = (const float*)d_in[3];
    const float* wk   = (const float*)d_in[4];
    const float* bk_  = (const float*)d_in[5];
    const float* wv   = (const float*)d_in[6];
    const float* bv   = (const float*)d_in[7];
    const float* wo   = (const float*)d_in[8];
    const float* bo   = (const float*)d_in[9];
    const float* w1   = (const float*)d_in[10];
    const float* b1   = (const float*)d_in[11];
    const float* w2   = (const float*)d_in[12];
    const float* b2   = (const float*)d_in[13];
    const float* a1   = (const float*)d_in[14];
    const float* be1  = (const float*)d_in[15];
    const float* a2   = (const float*)d_in[16];
    const float* be2  = (const float*)d_in[17];
    float* out = (float*)d_out;

    float *ln, *q, *kb, *v, *vT, *attn, *x2, *hb, *sc;
    cudaGetSymbolAddress((void**)&ln,   g_ln);
    cudaGetSymbolAddress((void**)&q,    g_q);
    cudaGetSymbolAddress((void**)&kb,   g_k);
    cudaGetSymbolAddress((void**)&v,    g_v);
    cudaGetSymbolAddress((void**)&vT,   g_vT);
    cudaGetSymbolAddress((void**)&attn, g_attn);
    cudaGetSymbolAddress((void**)&x2,   g_x2);
    cudaGetSymbolAddress((void**)&hb,   g_hbuf);
    cudaGetSymbolAddress((void**)&sc,   g_scores);

    constexpr int SM128 = 3 * (128 + 128) * 32 * 4;   // 98304
    constexpr int SM64  = 3 * (128 + 64) * 32 * 4;    // 73728
    cudaFuncSetAttribute(mma_gemm<128, false>, cudaFuncAttributeMaxDynamicSharedMemorySize, SM128);
    cudaFuncSetAttribute(mma_gemm<128, true>,  cudaFuncAttributeMaxDynamicSharedMemorySize, SM128);
    cudaFuncSetAttribute(mma_gemm<64, false>,  cudaFuncAttributeMaxDynamicSharedMemorySize, SM64);

    const long long sSD  = (long long)S_ * D_;
    const long long sSS  = (long long)S_ * S_;
    const long long sHSS = (long long)H_ * sSS;

    // 1. LN1
    layernorm_kernel<<<ROWS_, 256>>>(x, ln, a1, be1);

    // 2-4. Q, K, V projections (NT, M=4096, N=1024, K=1024)
    mma_gemm<128, false><<<dim3(D_ / 128, ROWS_ / 128, 1), 256, SM128>>>(
        ln, wq, bq, nullptr, q, D_, D_, D_, D_, 1, 0, 0, 0, 0, 0, 0, 1.0f);
    mma_gemm<128, false><<<dim3(D_ / 128, ROWS_ / 128, 1), 256, SM128>>>(
        ln, wk, bk_, nullptr, kb, D_, D_, D_, D_, 1, 0, 0, 0, 0, 0, 0, 1.0f);
    mma_gemm<128, false><<<dim3(D_ / 128, ROWS_ / 128, 1), 256, SM128>>>(
        ln, wv, bv, nullptr, v, D_, D_, D_, D_, 1, 0, 0, 0, 0, 0, 0, 1.0f);

    // 5. vT[(b,h)][n][s] = v[b][s][h*64+n]
    transpose_v_kernel<<<dim3(S_ / 32, DK_ / 32, B_ * H_), dim3(32, 8)>>>(v, vT);

    // 6. scores = (Q @ K^T)/8 (batched NT, M=N=2048, K=64)
    mma_gemm<128, false><<<dim3(S_ / 128, S_ / 128, B_ * H_), 256, SM128>>>(
        q, kb, nullptr, nullptr, sc, DK_, D_, D_, S_,
        H_, sSD, (long long)DK_, sSD, (long long)DK_, sHSS, sSS, 0.125f);

    // 7. masked softmax
    softmax_kernel<<<dim3(S_, B_ * H_), 256>>>(sc, msk);

    // 8. attn = P @ vT^T (batched NT, M=2048, N=64, K=2048)
    mma_gemm<64, false><<<dim3(1, S_ / 128, B_ * H_), 256, SM64>>>(
        sc, vT, nullptr, nullptr, attn, S_, S_, S_, D_,
        H_, sHSS, sSS, (long long)(H_ * DK_) * S_, (long long)DK_ * S_,
        sSD, (long long)DK_, 1.0f);

    // 9. x2 = attn @ wo^T + bo + x
    mma_gemm<128, false><<<dim3(D_ / 128, ROWS_ / 128, 1), 256, SM128>>>(
        attn, wo, bo, x, x2, D_, D_, D_, D_, 1, 0, 0, 0, 0, 0, 0, 1.0f);

    // 10. LN2
    layernorm_kernel<<<ROWS_, 256>>>(x2, ln, a2, be2);

    // 11. h = relu(ln @ w1^T + b1)  (M=4096, N=4096, K=1024)
    mma_gemm<128, true><<<dim3(DFF_ / 128, ROWS_ / 128, 1), 256, SM128>>>(
        ln, w1, b1, nullptr, hb, D_, D_, D_, DFF_, 1, 0, 0, 0, 0, 0, 0, 1.0f);

    // 12. out = h @ w2^T + b2 + x2  (M=4096, N=1024, K=4096)
    mma_gemm<128, false><<<dim3(D_ / 128, ROWS_ / 128, 1), 256, SM128>>>(
        hb, w2, b2, x2, out, DFF_, DFF_, DFF_, D_, 1, 0, 0, 0, 0, 0, 0, 1.0f);
}

// round 4
// speedup vs baseline: 4.0621x; 1.3573x over previous
#include <cuda_runtime.h>
#include <cstdint>

// ---------------------------------------------------------------------------
// EncoderBlock: pre-norm transformer block.
// GEMMs via mma.sync m16n8k8 tf32; fused flash-attention middle.
// B=2, S=2048, D=1024, H=16, DK=64, DFF=4096
// ---------------------------------------------------------------------------

namespace {
constexpr int B_ = 2, S_ = 2048, D_ = 1024, H_ = 16, DK_ = 64, DFF_ = 4096;
constexpr int ROWS_ = B_ * S_;            // 4096
constexpr float EPS_ = 1e-6f;
}

// Scratch (allocation-free: __device__ globals)
__device__ __align__(16) float g_ln[ROWS_ * D_];
__device__ __align__(16) float g_q[ROWS_ * D_];
__device__ __align__(16) float g_k[ROWS_ * D_];
__device__ __align__(16) float g_v[ROWS_ * D_];
__device__ __align__(16) float g_vT[B_ * H_ * DK_ * S_];
__device__ __align__(16) float g_attn[ROWS_ * D_];
__device__ __align__(16) float g_x2[ROWS_ * D_];
__device__ __align__(16) float g_hbuf[ROWS_ * DFF_];
__device__ __align__(16) float g_wr[12 * 1024 * 1024];   // rounded weights (48MB)

// ---------------------------------------------------------------------------
// PTX helpers
// ---------------------------------------------------------------------------
__device__ __forceinline__ uint32_t smem_u32(const void* p) {
    uint32_t a;
    asm("{ .reg .u64 t; cvta.to.shared.u64 t, %1; cvt.u32.u64 %0, t; }"
        : "=r"(a) : "l"(p));
    return a;
}

__device__ __forceinline__ void cp_async16(uint32_t s, const void* g) {
    asm volatile("cp.async.cg.shared.global [%0], [%1], 16;" :: "r"(s), "l"(g));
}
#define CP_COMMIT() asm volatile("cp.async.commit_group;" ::: "memory")
#define CP_WAIT(n)  asm volatile("cp.async.wait_group %0;" :: "n"(n) : "memory")

__device__ __forceinline__ uint32_t f2tf32(float f) {
    uint32_t u;
    asm("cvt.rna.tf32.f32 %0, %1;" : "=r"(u) : "f"(f));
    return u;
}
__device__ __forceinline__ float rndtf(float f) { return __uint_as_float(f2tf32(f)); }

__device__ __forceinline__ void mma_tf32(float* c, const uint32_t* a, const uint32_t* b) {
    asm volatile(
        "mma.sync.aligned.m16n8k8.row.col.f32.tf32.tf32.f32 "
        "{%0,%1,%2,%3}, {%4,%5,%6,%7}, {%8,%9}, {%0,%1,%2,%3};"
        : "+f"(c[0]), "+f"(c[1]), "+f"(c[2]), "+f"(c[3])
        : "r"(a[0]), "r"(a[1]), "r"(a[2]), "r"(a[3]), "r"(b[0]), "r"(b[1]));
}

// ---------------------------------------------------------------------------
// Weight pre-rounding (fp32 -> tf32-rounded fp32)
// ---------------------------------------------------------------------------
__global__ void round_tf32_kernel(const float* __restrict__ src, float* __restrict__ dst) {
    const int i = blockIdx.x * 256 + threadIdx.x;
    float4 v = reinterpret_cast<const float4*>(src)[i];
    v.x = rndtf(v.x); v.y = rndtf(v.y); v.z = rndtf(v.z); v.w = rndtf(v.w);
    reinterpret_cast<float4*>(dst)[i] = v;
}

// ---------------------------------------------------------------------------
// LayerNorm (exact fp32): unbiased std (ddof=1), scalar alpha/beta
// Output optionally tf32-rounded (it feeds GEMM operands).
// ---------------------------------------------------------------------------
__global__ void layernorm_kernel(const float* __restrict__ x, float* __restrict__ y,
                                 const float* __restrict__ alpha,
                                 const float* __restrict__ beta) {
    __shared__ float red_s[256];
    __shared__ float red_q[256];
    const int tid = threadIdx.x;
    const size_t off = (size_t)blockIdx.x * D_;
    float4 r = reinterpret_cast<const float4*>(x + off)[tid];
    float s = r.x + r.y + r.z + r.w;
    float q = r.x * r.x + r.y * r.y + r.z * r.z + r.w * r.w;
    red_s[tid] = s;
    red_q[tid] = q;
    __syncthreads();
    #pragma unroll
    for (int st = 128; st > 0; st >>= 1) {
        if (tid < st) { red_s[tid] += red_s[tid + st]; red_q[tid] += red_q[tid + st]; }
        __syncthreads();
    }
    const float mean = red_s[0] * (1.0f / D_);
    float var = (red_q[0] - (float)D_ * mean * mean) * (1.0f / (float)(D_ - 1));
    var = fmaxf(var, 0.0f);
    const float sc = alpha[0] / (sqrtf(var) + EPS_);
    const float sh = beta[0];
    float4 o;
    o.x = rndtf((r.x - mean) * sc + sh);
    o.y = rndtf((r.y - mean) * sc + sh);
    o.z = rndtf((r.z - mean) * sc + sh);
    o.w = rndtf((r.w - mean) * sc + sh);
    reinterpret_cast<float4*>(y + off)[tid] = o;
}

// ---------------------------------------------------------------------------
// V transpose: vT[(b*H+h)][n][s] = v[b][s][h*DK+n]  (v already tf32-rounded)
// ---------------------------------------------------------------------------
__global__ void transpose_v_kernel(const float* __restrict__ v, float* __restrict__ vT) {
    __shared__ float t[32][33];
    const int bh = blockIdx.z;
    const int b = bh / H_, h = bh % H_;
    const int s0 = blockIdx.x * 32, n0 = blockIdx.y * 32;
    const int tx = threadIdx.x, ty = threadIdx.y;   // 32 x 8
    const float* src = v + ((long long)b * S_ + s0) * D_ + h * DK_ + n0;
    #pragma unroll
    for (int i = 0; i < 32; i += 8)
        t[ty + i][tx] = src[(long long)(ty + i) * D_ + tx];
    __syncthreads();
    float* dst = vT + ((long long)bh * DK_ + n0) * S_ + s0;
    #pragma unroll
    for (int i = 0; i < 32; i += 8)
        dst[(long long)(ty + i) * S_ + tx] = t[tx][ty + i];
}

// ---------------------------------------------------------------------------
// tf32 tensor-core GEMM (NT). Operands PRE-ROUNDED to tf32 -> raw-bit loads.
// Block 128(M) x 128(N) x 32(K). 8 warps (2x4). 3-stage cp.async pipeline.
// ---------------------------------------------------------------------------
template <bool RELU, bool ROUNDOUT>
__global__ void __launch_bounds__(256, 2)
mma_gemm(const float* __restrict__ A, const float* __restrict__ Bm,
         const float* __restrict__ bias, const float* __restrict__ res,
         float* __restrict__ C,
         int K, int lda, int ldb, int ldc, float scale) {
    constexpr int STGF = 256 * 32;          // floats per stage
    constexpr int BOFF = 128 * 32;

    extern __shared__ float sm[];

    const int tid = threadIdx.x;
    const int wid = tid >> 5;
    const int lane = tid & 31;
    const int grp = lane >> 2;
    const int tid4 = lane & 3;
    const int wm0 = (wid >> 2) * 64;
    const int wn0 = (wid & 3) * 32;

    const int row0 = blockIdx.y * 128;
    const int col0 = blockIdx.x * 128;

    int aGo[4]; uint32_t aSm[4];
    #pragma unroll
    for (int l = 0; l < 4; l++) {
        const int idx4 = tid + l * 256;
        const int r = idx4 >> 3, ch = idx4 & 7;
        aGo[l] = (row0 + r) * lda + ch * 4;
        aSm[l] = (uint32_t)(r * 32 + ((ch ^ (r & 7)) << 2)) * 4u;
    }
    int bGo[4]; uint32_t bSm[4];
    #pragma unroll
    for (int l = 0; l < 4; l++) {
        const int idx4 = tid + l * 256;
        const int r = idx4 >> 3, ch = idx4 & 7;
        bGo[l] = (col0 + r) * ldb + ch * 4;
        bSm[l] = (uint32_t)(BOFF + r * 32 + ((ch ^ (r & 7)) << 2)) * 4u;
    }
    const uint32_t smBase = smem_u32(sm);

    float acc[4][4][4];
    #pragma unroll
    for (int i = 0; i < 4; i++)
        #pragma unroll
        for (int j = 0; j < 4; j++)
            #pragma unroll
            for (int e = 0; e < 4; e++) acc[i][j][e] = 0.0f;

    const int nch = K / 32;

    #pragma unroll
    for (int s = 0; s < 2; s++) {
        const uint32_t sb = smBase + (uint32_t)(s % 3) * STGF * 4u;
        const int k0 = s * 32;
        #pragma unroll
        for (int l = 0; l < 4; l++) cp_async16(sb + aSm[l], A + aGo[l] + k0);
        #pragma unroll
        for (int l = 0; l < 4; l++) cp_async16(sb + bSm[l], Bm + bGo[l] + k0);
        CP_COMMIT();
    }

    for (int ci = 0; ci < nch; ci++) {
        if (ci + 2 < nch) { CP_WAIT(1); } else { CP_WAIT(0); }
        __syncthreads();
        if (ci + 2 < nch) {
            const int s = ci + 2;
            const uint32_t sb = smBase + (uint32_t)(s % 3) * STGF * 4u;
            const int k0 = s * 32;
            #pragma unroll
            for (int l = 0; l < 4; l++) cp_async16(sb + aSm[l], A + aGo[l] + k0);
            #pragma unroll
            for (int l = 0; l < 4; l++) cp_async16(sb + bSm[l], Bm + bGo[l] + k0);
            CP_COMMIT();
        }

        const uint32_t* Abuf = reinterpret_cast<const uint32_t*>(sm + (ci % 3) * STGF);
        const uint32_t* Bbuf = Abuf + BOFF;

        #pragma unroll
        for (int ks = 0; ks < 4; ks++) {
            const int ce = ((ks * 2) ^ grp) << 2;
            const int co = ((ks * 2 + 1) ^ grp) << 2;
            uint32_t a[4][4];
            #pragma unroll
            for (int ma = 0; ma < 4; ma++) {
                const int r0 = (wm0 + ma * 16 + grp) * 32;
                a[ma][0] = Abuf[r0 + ce + tid4];
                a[ma][1] = Abuf[r0 + 256 + ce + tid4];
                a[ma][2] = Abuf[r0 + co + tid4];
                a[ma][3] = Abuf[r0 + 256 + co + tid4];
            }
            uint32_t b[4][2];
            #pragma unroll
            for (int na = 0; na < 4; na++) {
                const int n0 = (wn0 + na * 8 + grp) * 32;
                b[na][0] = Bbuf[n0 + ce + tid4];
                b[na][1] = Bbuf[n0 + co + tid4];
            }
            #pragma unroll
            for (int ma = 0; ma < 4; ma++)
                #pragma unroll
                for (int na = 0; na < 4; na++)
                    mma_tf32(acc[ma][na], a[ma], b[na]);
        }
    }

    #pragma unroll
    for (int ma = 0; ma < 4; ma++) {
        const int rr = row0 + wm0 + ma * 16 + grp;
        #pragma unroll
        for (int na = 0; na < 4; na++) {
            const int cc = col0 + wn0 + na * 8 + tid4 * 2;
            float2 v0, v1;
            v0.x = acc[ma][na][0] * scale; v0.y = acc[ma][na][1] * scale;
            v1.x = acc[ma][na][2] * scale; v1.y = acc[ma][na][3] * scale;
            if (bias) {
                const float2 bv = *reinterpret_cast<const float2*>(bias + cc);
                v0.x += bv.x; v0.y += bv.y; v1.x += bv.x; v1.y += bv.y;
            }
            if (RELU) {
                v0.x = fmaxf(v0.x, 0.0f); v0.y = fmaxf(v0.y, 0.0f);
                v1.x = fmaxf(v1.x, 0.0f); v1.y = fmaxf(v1.y, 0.0f);
            }
            if (ROUNDOUT) {
                v0.x = rndtf(v0.x); v0.y = rndtf(v0.y);
                v1.x = rndtf(v1.x); v1.y = rndtf(v1.y);
            }
            const long long o0 = (long long)rr * ldc + cc;
            const long long o1 = (long long)(rr + 8) * ldc + cc;
            if (res) {
                const float2 r0 = *reinterpret_cast<const float2*>(res + o0);
                const float2 r1 = *reinterpret_cast<const float2*>(res + o1);
                v0.x += r0.x; v0.y += r0.y; v1.x += r1.x; v1.y += r1.y;
            }
            *reinterpret_cast<float2*>(C + o0) = v0;
            *reinterpret_cast<float2*>(C + o1) = v1;
        }
    }
}

// ---------------------------------------------------------------------------
// Fused flash attention: per (bh, 128-q-tile) block.
//   S = (Q K^T)/8, mask==0 -> -1e9, online softmax, O = P V, normalize.
// Q/K/VT are tf32-pre-rounded in gmem; P is rna-rounded before PV MMA.
// Output g_attn written tf32-rounded (feeds Wo GEMM).
// SMEM (floats): Q[128x64], K dbl[2x128x64], VT[64x128], P[128x128],
//                mask[2048 int], red[128x4], M/L/Corr[128 each].
// ---------------------------------------------------------------------------
namespace fa {
constexpr int oQ = 0, oK = 8192, oVT = 24576, oP = 32768;
constexpr int oMask = 49152, oRed = 51200, oM = 51712, oL = 51840, oCorr = 51968;
constexpr int FTOT = 52096;                    // floats
constexpr int SMEM_BYTES = FTOT * 4;           // 208384
}

__global__ void __launch_bounds__(256)
flash_attn_kernel(const float* __restrict__ q, const float* __restrict__ k,
                  const float* __restrict__ vT, const int* __restrict__ mask,
                  float* __restrict__ attn) {
    using namespace fa;
    extern __shared__ float sm[];
    int* smask = reinterpret_cast<int*>(sm + oMask);
    const uint32_t* smu = reinterpret_cast<const uint32_t*>(sm);
    const uint32_t smb = smem_u32(sm);

    const int tid = threadIdx.x, wid = tid >> 5, lane = tid & 31;
    const int grp = lane >> 2, tid4 = lane & 3;
    // S-phase warp layout: 2(M) x 4(N)
    const int wm0 = (wid >> 2) * 64;
    const int wn0 = (wid & 3) * 32;
    // PV-phase warp layout: 4(M) x 2(N)
    const int wmB = (wid >> 1) * 32;
    const int wnB = (wid & 1) * 32;

    const int qt = blockIdx.x;
    const int bh = blockIdx.y;
    const int b = bh >> 4, hh = bh & 15;
    const int q0 = qt * 128;
    const float* Qg = q + ((size_t)(b * S_ + q0)) * D_ + hh * 64;
    const float* Kg = k + ((size_t)(b * S_)) * D_ + hh * 64;
    const float* Vg = vT + (size_t)bh * 64 * S_;

    if (tid < 128) { sm[oM + tid] = -3.0e38f; sm[oL + tid] = 0.0f; }
    #pragma unroll
    for (int l = 0; l < 8; l++) smask[tid + l * 256] = mask[b * S_ + tid + l * 256];

    // prologue: group0 = {Q, K0}, group1 = {VT0}
    #pragma unroll
    for (int l = 0; l < 8; l++) {
        const int i4 = tid + l * 256;
        const int r = i4 >> 4, c = i4 & 15;
        cp_async16(smb + (uint32_t)(oQ + r * 64 + ((c ^ (r & 7)) << 2)) * 4u,
                   Qg + (size_t)r * D_ + c * 4);
    }
    #pragma unroll
    for (int l = 0; l < 8; l++) {
        const int i4 = tid + l * 256;
        const int r = i4 >> 4, c = i4 & 15;
        cp_async16(smb + (uint32_t)(oK + r * 64 + ((c ^ (r & 7)) << 2)) * 4u,
                   Kg + (size_t)r * D_ + c * 4);
    }
    CP_COMMIT();
    #pragma unroll
    for (int l = 0; l < 8; l++) {
        const int i4 = tid + l * 256;
        const int r = i4 >> 5, c = i4 & 31;
        cp_async16(smb + (uint32_t)(oVT + r * 128 + ((c ^ (r & 7)) << 2)) * 4u,
                   Vg + (size_t)r * S_ + c * 4);
    }
    CP_COMMIT();

    float acc_o[2][4][4];
    #pragma unroll
    for (int i = 0; i < 2; i++)
        #pragma unroll
        for (int j = 0; j < 4; j++)
            #pragma unroll
            for (int e = 0; e < 4; e++) acc_o[i][j][e] = 0.0f;

    constexpr int NIT = S_ / 128;   // 16

    for (int it = 0; it < NIT; ++it) {
        const int kv0 = it * 128;
        CP_WAIT(1);                 // K(it) (+Q on it==0) ready; <=1 pending (VT(it))
        __syncthreads();

        // ---- S = Q K^T (M=128, N=128, K=64) ----
        float acc_s[4][4][4];
        #pragma unroll
        for (int i = 0; i < 4; i++)
            #pragma unroll
            for (int j = 0; j < 4; j++)
                #pragma unroll
                for (int e = 0; e < 4; e++) acc_s[i][j][e] = 0.0f;

        const int oKb = oK + (it & 1) * 8192;
        #pragma unroll
        for (int ks = 0; ks < 8; ks++) {
            const int ce = ((ks * 2) ^ grp) << 2;
            const int co = ((ks * 2 + 1) ^ grp) << 2;
            uint32_t a[4][4];
            #pragma unroll
            for (int ma = 0; ma < 4; ma++) {
                const int r0 = oQ + (wm0 + ma * 16 + grp) * 64;
                a[ma][0] = smu[r0 + ce + tid4];
                a[ma][1] = smu[r0 + 512 + ce + tid4];
                a[ma][2] = smu[r0 + co + tid4];
                a[ma][3] = smu[r0 + 512 + co + tid4];
            }
            uint32_t bf[4][2];
            #pragma unroll
            for (int na = 0; na < 4; na++) {
                const int n0 = oKb + (wn0 + na * 8 + grp) * 64;
                bf[na][0] = smu[n0 + ce + tid4];
                bf[na][1] = smu[n0 + co + tid4];
            }
            #pragma unroll
            for (int ma = 0; ma < 4; ma++)
                #pragma unroll
                for (int na = 0; na < 4; na++)
                    mma_tf32(acc_s[ma][na], a[ma], bf[na]);
        }

        // prefetch K(it+1) into other buffer (no barrier needed: disjoint buffer)
        if (it + 1 < NIT) {
            const uint32_t kb = smb + (uint32_t)(oK + ((it + 1) & 1) * 8192) * 4u;
            const float* Kn = Kg + (size_t)(kv0 + 128) * D_;
            #pragma unroll
            for (int l = 0; l < 8; l++) {
                const int i4 = tid + l * 256;
                const int r = i4 >> 4, c = i4 & 15;
                cp_async16(kb + (uint32_t)(r * 64 + ((c ^ (r & 7)) << 2)) * 4u,
                           Kn + (size_t)r * D_ + c * 4);
            }
            CP_COMMIT();
        }

        // ---- mask + scale ----
        #pragma unroll
        for (int na = 0; na < 4; na++) {
            const int cg = kv0 + wn0 + na * 8 + tid4 * 2;
            const bool m0 = smask[cg] != 0;
            const bool m1 = smask[cg + 1] != 0;
            #pragma unroll
            for (int ma = 0; ma < 4; ma++) {
                float* s = acc_s[ma][na];
                s[0] = m0 ? s[0] * 0.125f : -1e9f;
                s[1] = m1 ? s[1] * 0.125f : -1e9f;
                s[2] = m0 ? s[2] * 0.125f : -1e9f;
                s[3] = m1 ? s[3] * 0.125f : -1e9f;
            }
        }

        // ---- row max: quad shfl + cross-warp smem ----
        float pmax[4][2];
        #pragma unroll
        for (int ma = 0; ma < 4; ma++) {
            float p0 = -3.0e38f, p1 = -3.0e38f;
            #pragma unroll
            for (int na = 0; na < 4; na++) {
                p0 = fmaxf(p0, fmaxf(acc_s[ma][na][0], acc_s[ma][na][1]));
                p1 = fmaxf(p1, fmaxf(acc_s[ma][na][2], acc_s[ma][na][3]));
            }
            #pragma unroll
            for (int d2 = 1; d2 < 4; d2 <<= 1) {
                p0 = fmaxf(p0, __shfl_xor_sync(0xffffffffu, p0, d2));
                p1 = fmaxf(p1, __shfl_xor_sync(0xffffffffu, p1, d2));
            }
            pmax[ma][0] = p0; pmax[ma][1] = p1;
        }
        if (tid4 == 0) {
            const int wc = wid & 3;
            #pragma unroll
            for (int ma = 0; ma < 4; ma++) {
                const int r = wm0 + ma * 16 + grp;
                sm[oRed + r * 4 + wc] = pmax[ma][0];
                sm[oRed + (r + 8) * 4 + wc] = pmax[ma][1];
            }
        }
        __syncthreads();
        if (tid < 128) {
            const float4 rv = *reinterpret_cast<const float4*>(&sm[oRed + tid * 4]);
            const float rmax = fmaxf(fmaxf(rv.x, rv.y), fmaxf(rv.z, rv.w));
            const float mo = sm[oM + tid];
            const float mn = fmaxf(mo, rmax);
            sm[oM + tid] = mn;
            sm[oCorr + tid] = __expf(mo - mn);
        }
        __syncthreads();

        // ---- p = exp(s - m), row sums, write rounded P tile ----
        float psum[4][2];
        #pragma unroll
        for (int ma = 0; ma < 4; ma++) {
            const int r = wm0 + ma * 16 + grp;
            const float m0 = sm[oM + r];
            const float m1 = sm[oM + r + 8];
            float s0sum = 0.0f, s1sum = 0.0f;
            #pragma unroll
            for (int na = 0; na < 4; na++) {
                float* s = acc_s[ma][na];
                s[0] = __expf(s[0] - m0);
                s[1] = __expf(s[1] - m0);
                s[2] = __expf(s[2] - m1);
                s[3] = __expf(s[3] - m1);
                s0sum += s[0] + s[1];
                s1sum += s[2] + s[3];
                const int ch = (wid & 3) * 8 + na * 2 + (tid4 >> 1);
                const int fo = oP + r * 128 + ((ch ^ grp) << 2) + ((tid4 & 1) << 1);
                float2 p0, p1;
                p0.x = rndtf(s[0]); p0.y = rndtf(s[1]);
                p1.x = rndtf(s[2]); p1.y = rndtf(s[3]);
                *reinterpret_cast<float2*>(&sm[fo]) = p0;
                *reinterpret_cast<float2*>(&sm[fo + 1024]) = p1;
            }
            #pragma unroll
            for (int d2 = 1; d2 < 4; d2 <<= 1) {
                s0sum += __shfl_xor_sync(0xffffffffu, s0sum, d2);
                s1sum += __shfl_xor_sync(0xffffffffu, s1sum, d2);
            }
            psum[ma][0] = s0sum; psum[ma][1] = s1sum;
        }
        if (tid4 == 0) {
            const int wc = wid & 3;
            #pragma unroll
            for (int ma = 0; ma < 4; ma++) {
                const int r = wm0 + ma * 16 + grp;
                sm[oRed + r * 4 + wc] = psum[ma][0];
                sm[oRed + (r + 8) * 4 + wc] = psum[ma][1];
            }
        }
        __syncthreads();
        if (tid < 128) {
            const float4 rv = *reinterpret_cast<const float4*>(&sm[oRed + tid * 4]);
            sm[oL + tid] = sm[oL + tid] * sm[oCorr + tid] + (rv.x + rv.y + rv.z + rv.w);
        }

        // ---- PV: O = corr*O + P @ VT^T (M=128, N=64, K=128) ----
        // correction
        #pragma unroll
        for (int ma = 0; ma < 2; ma++) {
            const int r = wmB + ma * 16 + grp;
            const float c0 = sm[oCorr + r];
            const float c1 = sm[oCorr + r + 8];
            #pragma unroll
            for (int na = 0; na < 4; na++) {
                acc_o[ma][na][0] *= c0; acc_o[ma][na][1] *= c0;
                acc_o[ma][na][2] *= c1; acc_o[ma][na][3] *= c1;
            }
        }
        // wait VT(it): <=1 pending (K(it+1)); last iter: nothing may pend
        if (it + 1 < NIT) { CP_WAIT(1); } else { CP_WAIT(0); }
        __syncthreads();

        #pragma unroll
        for (int ks = 0; ks < 16; ks++) {
            const int ce = ((ks * 2) ^ grp) << 2;
            const int co = ((ks * 2 + 1) ^ grp) << 2;
            uint32_t a[2][4];
            #pragma unroll
            for (int ma = 0; ma < 2; ma++) {
                const int r0 = oP + (wmB + ma * 16 + grp) * 128;
                a[ma][0] = smu[r0 + ce + tid4];
                a[ma][1] = smu[r0 + 1024 + ce + tid4];
                a[ma][2] = smu[r0 + co + tid4];
                a[ma][3] = smu[r0 + 1024 + co + tid4];
            }
            uint32_t bf[4][2];
            #pragma unroll
            for (int na = 0; na < 4; na++) {
                const int n0 = oVT + (wnB + na * 8 + grp) * 128;
                bf[na][0] = smu[n0 + ce + tid4];
                bf[na][1] = smu[n0 + co + tid4];
            }
            #pragma unroll
            for (int ma = 0; ma < 2; ma++)
                #pragma unroll
                for (int na = 0; na < 4; na++)
                    mma_tf32(acc_o[ma][na], a[ma], bf[na]);
        }
        __syncthreads();   // all PV reads done before VT(it+1) overwrites

        if (it + 1 < NIT) {
            const float* Vn = Vg + kv0 + 128;
            #pragma unroll
            for (int l = 0; l < 8; l++) {
                const int i4 = tid + l * 256;
                const int r = i4 >> 5, c = i4 & 31;
                cp_async16(smb + (uint32_t)(oVT + r * 128 + ((c ^ (r & 7)) << 2)) * 4u,
                           Vn + (size_t)r * S_ + c * 4);
            }
            CP_COMMIT();
        }
    }

    // ---- normalize and store (tf32-rounded; feeds Wo GEMM) ----
    #pragma unroll
    for (int ma = 0; ma < 2; ma++) {
        const int r = wmB + ma * 16 + grp;
        const float inv0 = 1.0f / sm[oL + r];
        const float inv1 = 1.0f / sm[oL + r + 8];
        #pragma unroll
        for (int na = 0; na < 4; na++) {
            const int cd = wnB + na * 8 + tid4 * 2;
            float2 v0, v1;
            v0.x = rndtf(acc_o[ma][na][0] * inv0);
            v0.y = rndtf(acc_o[ma][na][1] * inv0);
            v1.x = rndtf(acc_o[ma][na][2] * inv1);
            v1.y = rndtf(acc_o[ma][na][3] * inv1);
            const size_t o0 = ((size_t)(b * S_ + q0 + r)) * D_ + hh * 64 + cd;
            const size_t o1 = o0 + (size_t)8 * D_;
            *reinterpret_cast<float2*>(attn + o0) = v0;
            *reinterpret_cast<float2*>(attn + o1) = v1;
        }
    }
}

// ---------------------------------------------------------------------------
// kernel_launch
// ---------------------------------------------------------------------------
extern "C" void kernel_launch(void* const* d_in, const int* in_sizes, int n_in,
                              void* d_out, int out_size) {
    const float* x    = (const float*)d_in[0];
    const int*   msk  = (const int*)  d_in[1];
    const float* wq   = (const float*)d_in[2];
    const float* bq   = (const float*)d_in[3];
    const float* wk   = (const float*)d_in[4];
    const float* bk_  = (const float*)d_in[5];
    const float* wv   = (const float*)d_in[6];
    const float* bv   = (const float*)d_in[7];
    const float* wo   = (const float*)d_in[8];
    const float* bo   = (const float*)d_in[9];
    const float* w1   = (const float*)d_in[10];
    const float* b1   = (const float*)d_in[11];
    const float* w2   = (const float*)d_in[12];
    const float* b2   = (const float*)d_in[13];
    const float* a1   = (const float*)d_in[14];
    const float* be1  = (const float*)d_in[15];
    const float* a2   = (const float*)d_in[16];
    const float* be2  = (const float*)d_in[17];
    float* out = (float*)d_out;

    float *ln, *q, *kb, *v, *vT, *attn, *x2, *hb, *wr;
    cudaGetSymbolAddress((void**)&ln,   g_ln);
    cudaGetSymbolAddress((void**)&q,    g_q);
    cudaGetSymbolAddress((void**)&kb,   g_k);
    cudaGetSymbolAddress((void**)&v,    g_v);
    cudaGetSymbolAddress((void**)&vT,   g_vT);
    cudaGetSymbolAddress((void**)&attn, g_attn);
    cudaGetSymbolAddress((void**)&x2,   g_x2);
    cudaGetSymbolAddress((void**)&hb,   g_hbuf);
    cudaGetSymbolAddress((void**)&wr,   g_wr);

    constexpr int M1 = 1024 * 1024;
    float* wqr = wr;            float* wkr = wr + M1;
    float* wvr = wr + 2 * M1;   float* wor = wr + 3 * M1;
    float* w1r = wr + 4 * M1;   float* w2r = wr + 8 * M1;

    constexpr int SMG = 3 * 256 * 32 * 4;   // 98304
    cudaFuncSetAttribute(mma_gemm<false, false>, cudaFuncAttributeMaxDynamicSharedMemorySize, SMG);
    cudaFuncSetAttribute(mma_gemm<false, true>,  cudaFuncAttributeMaxDynamicSharedMemorySize, SMG);
    cudaFuncSetAttribute(mma_gemm<true,  true>,  cudaFuncAttributeMaxDynamicSharedMemorySize, SMG);
    cudaFuncSetAttribute(flash_attn_kernel, cudaFuncAttributeMaxDynamicSharedMemorySize,
                         fa::SMEM_BYTES);

    // 0. pre-round weights to tf32
    round_tf32_kernel<<<M1 / 1024, 256>>>(wq, wqr);
    round_tf32_kernel<<<M1 / 1024, 256>>>(wk, wkr);
    round_tf32_kernel<<<M1 / 1024, 256>>>(wv, wvr);
    round_tf32_kernel<<<M1 / 1024, 256>>>(wo, wor);
    round_tf32_kernel<<<4 * M1 / 1024, 256>>>(w1, w1r);
    round_tf32_kernel<<<4 * M1 / 1024, 256>>>(w2, w2r);

    // 1. LN1 (tf32-rounded output)
    layernorm_kernel<<<ROWS_, 256>>>(x, ln, a1, be1);

    // 2-4. Q, K, V projections (rounded outputs; feed attention MMAs)
    mma_gemm<false, true><<<dim3(D_ / 128, ROWS_ / 128), 256, SMG>>>(
        ln, wqr, bq, nullptr, q, D_, D_, D_, D_, 1.0f);
    mma_gemm<false, true><<<dim3(D_ / 128, ROWS_ / 128), 256, SMG>>>(
        ln, wkr, bk_, nullptr, kb, D_, D_, D_, D_, 1.0f);
    mma_gemm<false, true><<<dim3(D_ / 128, ROWS_ / 128), 256, SMG>>>(
        ln, wvr, bv, nullptr, v, D_, D_, D_, D_, 1.0f);

    // 5. vT
    transpose_v_kernel<<<dim3(S_ / 32, DK_ / 32, B_ * H_), dim3(32, 8)>>>(v, vT);

    // 6. fused flash attention -> attn (rounded)
    flash_attn_kernel<<<dim3(S_ / 128, B_ * H_), 256, fa::SMEM_BYTES>>>(
        q, kb, vT, msk, attn);

    // 7. x2 = attn @ wo^T + bo + x
    mma_gemm<false, false><<<dim3(D_ / 128, ROWS_ / 128), 256, SMG>>>(
        attn, wor, bo, x, x2, D_, D_, D_, D_, 1.0f);

    // 8. LN2 (rounded)
    layernorm_kernel<<<ROWS_, 256>>>(x2, ln, a2, be2);

    // 9. h = relu(ln @ w1^T + b1) (rounded)
    mma_gemm<true, true><<<dim3(DFF_ / 128, ROWS_ / 128), 256, SMG>>>(
        ln, w1r, b1, nullptr, hb, D_, D_, D_, DFF_, 1.0f);

    // 10. out = h @ w2^T + b2 + x2
    mma_gemm<false, false><<<dim3(D_ / 128, ROWS_ / 128), 256, SMG>>>(
        hb, w2r, b2, x2, out, DFF_, DFF_, DFF_, D_, 1.0f);
}

// round 5
// speedup vs baseline: 4.3169x; 1.0627x over previous
#include <cuda_runtime.h>
#include <cstdint>

// ---------------------------------------------------------------------------
// EncoderBlock: pre-norm transformer block.
// GEMMs via mma.sync m16n8k8 tf32 + ldmatrix fragments; fused flash attention.
// B=2, S=2048, D=1024, H=16, DK=64, DFF=4096
// ---------------------------------------------------------------------------

namespace {
constexpr int B_ = 2, S_ = 2048, D_ = 1024, H_ = 16, DK_ = 64, DFF_ = 4096;
constexpr int ROWS_ = B_ * S_;            // 4096
constexpr float EPS_ = 1e-6f;
}

// Scratch (allocation-free: __device__ globals)
__device__ __align__(16) float g_ln[ROWS_ * D_];
__device__ __align__(16) float g_q[ROWS_ * D_];
__device__ __align__(16) float g_k[ROWS_ * D_];
__device__ __align__(16) float g_v[ROWS_ * D_];
__device__ __align__(16) float g_vT[B_ * H_ * DK_ * S_];
__device__ __align__(16) float g_attn[ROWS_ * D_];
__device__ __align__(16) float g_x2[ROWS_ * D_];
__device__ __align__(16) float g_hbuf[ROWS_ * DFF_];
__device__ __align__(16) float g_wr[12 * 1024 * 1024];   // rounded weights (48MB)

// ---------------------------------------------------------------------------
// PTX helpers
// ---------------------------------------------------------------------------
__device__ __forceinline__ uint32_t smem_u32(const void* p) {
    uint32_t a;
    asm("{ .reg .u64 t; cvta.to.shared.u64 t, %1; cvt.u32.u64 %0, t; }"
        : "=r"(a) : "l"(p));
    return a;
}

__device__ __forceinline__ void cp_async16(uint32_t s, const void* g) {
    asm volatile("cp.async.cg.shared.global [%0], [%1], 16;" :: "r"(s), "l"(g));
}
#define CP_COMMIT() asm volatile("cp.async.commit_group;" ::: "memory")
#define CP_WAIT(n)  asm volatile("cp.async.wait_group %0;" :: "n"(n) : "memory")

__device__ __forceinline__ uint32_t f2tf32(float f) {
    uint32_t u;
    asm("cvt.rna.tf32.f32 %0, %1;" : "=r"(u) : "f"(f));
    return u;
}
__device__ __forceinline__ float rndtf(float f) { return __uint_as_float(f2tf32(f)); }

__device__ __forceinline__ void mma_tf32(float* c, const uint32_t* a, const uint32_t* b) {
    asm volatile(
        "mma.sync.aligned.m16n8k8.row.col.f32.tf32.tf32.f32 "
        "{%0,%1,%2,%3}, {%4,%5,%6,%7}, {%8,%9}, {%0,%1,%2,%3};"
        : "+f"(c[0]), "+f"(c[1]), "+f"(c[2]), "+f"(c[3])
        : "r"(a[0]), "r"(a[1]), "r"(a[2]), "r"(a[3]), "r"(b[0]), "r"(b[1]));
}

// ldmatrix x4: 4 8-row x 16-byte matrices; thread t supplies row t%8 of matrix t/8.
__device__ __forceinline__ void ldsm_x4(uint32_t* r, uint32_t saddr) {
    asm volatile("ldmatrix.sync.aligned.m8n8.x4.shared.b16 {%0,%1,%2,%3}, [%4];"
                 : "=r"(r[0]), "=r"(r[1]), "=r"(r[2]), "=r"(r[3]) : "r"(saddr));
}

// ---------------------------------------------------------------------------
// Fused weight pre-rounding (fp32 -> tf32-rounded fp32), all 6 weights
// dst layout: [wq 1M][wk 1M][wv 1M][wo 1M][w1 4M][w2 4M] floats
// ---------------------------------------------------------------------------
__global__ void round_all_kernel(const float* __restrict__ wq, const float* __restrict__ wk,
                                 const float* __restrict__ wv, const float* __restrict__ wo,
                                 const float* __restrict__ w1, const float* __restrict__ w2,
                                 float* __restrict__ dst) {
    constexpr int M1 = 1024 * 1024;
    const int y = blockIdx.y;
    const int small = (y < 4);
    if (small && blockIdx.x >= 1024) return;
    const float* src;
    size_t off;
    switch (y) {
        case 0: src = wq; off = 0; break;
        case 1: src = wk; off = (size_t)M1; break;
        case 2: src = wv; off = 2 * (size_t)M1; break;
        case 3: src = wo; off = 3 * (size_t)M1; break;
        case 4: src = w1; off = 4 * (size_t)M1; break;
        default: src = w2; off = 8 * (size_t)M1; break;
    }
    const int i = blockIdx.x * 256 + threadIdx.x;
    float4 v = reinterpret_cast<const float4*>(src)[i];
    v.x = rndtf(v.x); v.y = rndtf(v.y); v.z = rndtf(v.z); v.w = rndtf(v.w);
    reinterpret_cast<float4*>(dst + off)[i] = v;
}

// ---------------------------------------------------------------------------
// LayerNorm (exact fp32): unbiased std (ddof=1), scalar alpha/beta.
// Output tf32-rounded (feeds GEMM operands).
// ---------------------------------------------------------------------------
__global__ void layernorm_kernel(const float* __restrict__ x, float* __restrict__ y,
                                 const float* __restrict__ alpha,
                                 const float* __restrict__ beta) {
    __shared__ float red_s[256];
    __shared__ float red_q[256];
    const int tid = threadIdx.x;
    const size_t off = (size_t)blockIdx.x * D_;
    float4 r = reinterpret_cast<const float4*>(x + off)[tid];
    float s = r.x + r.y + r.z + r.w;
    float q = r.x * r.x + r.y * r.y + r.z * r.z + r.w * r.w;
    red_s[tid] = s;
    red_q[tid] = q;
    __syncthreads();
    #pragma unroll
    for (int st = 128; st > 0; st >>= 1) {
        if (tid < st) { red_s[tid] += red_s[tid + st]; red_q[tid] += red_q[tid + st]; }
        __syncthreads();
    }
    const float mean = red_s[0] * (1.0f / D_);
    float var = (red_q[0] - (float)D_ * mean * mean) * (1.0f / (float)(D_ - 1));
    var = fmaxf(var, 0.0f);
    const float sc = alpha[0] / (sqrtf(var) + EPS_);
    const float sh = beta[0];
    float4 o;
    o.x = rndtf((r.x - mean) * sc + sh);
    o.y = rndtf((r.y - mean) * sc + sh);
    o.z = rndtf((r.z - mean) * sc + sh);
    o.w = rndtf((r.w - mean) * sc + sh);
    reinterpret_cast<float4*>(y + off)[tid] = o;
}

// ---------------------------------------------------------------------------
// V transpose: vT[(b*H+h)][n][s] = v[b][s][h*DK+n]
// ---------------------------------------------------------------------------
__global__ void transpose_v_kernel(const float* __restrict__ v, float* __restrict__ vT) {
    __shared__ float t[32][33];
    const int bh = blockIdx.z;
    const int b = bh / H_, h = bh % H_;
    const int s0 = blockIdx.x * 32, n0 = blockIdx.y * 32;
    const int tx = threadIdx.x, ty = threadIdx.y;   // 32 x 8
    const float* src = v + ((long long)b * S_ + s0) * D_ + h * DK_ + n0;
    #pragma unroll
    for (int i = 0; i < 32; i += 8)
        t[ty + i][tx] = src[(long long)(ty + i) * D_ + tx];
    __syncthreads();
    float* dst = vT + ((long long)bh * DK_ + n0) * S_ + s0;
    #pragma unroll
    for (int i = 0; i < 32; i += 8)
        dst[(long long)(ty + i) * S_ + tx] = t[tx][ty + i];
}

// ---------------------------------------------------------------------------
// tf32 tensor-core GEMM (NT). Operands PRE-ROUNDED to tf32 -> raw-bit LDSM.
// Block 128(M) x 128(N) x 32(K). 8 warps (2x4). 3-stage cp.async pipeline.
// ---------------------------------------------------------------------------
template <bool RELU, bool ROUNDOUT>
__global__ void __launch_bounds__(256, 2)
mma_gemm(const float* __restrict__ A, const float* __restrict__ Bm,
         const float* __restrict__ bias, const float* __restrict__ res,
         float* __restrict__ C,
         int K, int lda, int ldb, int ldc, float scale) {
    constexpr int STGF = 256 * 32;          // floats per stage
    constexpr int BOFF = 128 * 32;

    extern __shared__ float sm[];

    const int tid = threadIdx.x;
    const int wid = tid >> 5;
    const int lane = tid & 31;
    const int grp = lane >> 2;
    const int tid4 = lane & 3;
    const int wm0 = (wid >> 2) * 64;
    const int wn0 = (wid & 3) * 32;

    // ldmatrix per-thread addressing (row low bits = lane&7 -> swizzle XOR l7)
    const int l7 = lane & 7;
    const int aRB = ((lane >> 3) & 1) * 8 + l7;   // A: m0/m2 rows lo, m1/m3 rows hi
    const int aCB = lane >> 4;                    // A: m0/m1 chunk even, m2/m3 odd
    const int bRB = ((lane >> 4) & 1) * 8 + l7;   // B: m0/m1 rows lo, m2/m3 rows hi
    const int bCB = (lane >> 3) & 1;              // B: m0/m2 chunk even, m1/m3 odd

    const int row0 = blockIdx.y * 128;
    const int col0 = blockIdx.x * 128;

    int aGo[4]; uint32_t aSm[4];
    #pragma unroll
    for (int l = 0; l < 4; l++) {
        const int idx4 = tid + l * 256;
        const int r = idx4 >> 3, ch = idx4 & 7;
        aGo[l] = (row0 + r) * lda + ch * 4;
        aSm[l] = (uint32_t)(r * 32 + ((ch ^ (r & 7)) << 2)) * 4u;
    }
    int bGo[4]; uint32_t bSm[4];
    #pragma unroll
    for (int l = 0; l < 4; l++) {
        const int idx4 = tid + l * 256;
        const int r = idx4 >> 3, ch = idx4 & 7;
        bGo[l] = (col0 + r) * ldb + ch * 4;
        bSm[l] = (uint32_t)(BOFF + r * 32 + ((ch ^ (r & 7)) << 2)) * 4u;
    }
    const uint32_t smBase = smem_u32(sm);

    float acc[4][4][4];
    #pragma unroll
    for (int i = 0; i < 4; i++)
        #pragma unroll
        for (int j = 0; j < 4; j++)
            #pragma unroll
            for (int e = 0; e < 4; e++) acc[i][j][e] = 0.0f;

    const int nch = K / 32;

    #pragma unroll
    for (int s = 0; s < 2; s++) {
        const uint32_t sb = smBase + (uint32_t)(s % 3) * STGF * 4u;
        const int k0 = s * 32;
        #pragma unroll
        for (int l = 0; l < 4; l++) cp_async16(sb + aSm[l], A + aGo[l] + k0);
        #pragma unroll
        for (int l = 0; l < 4; l++) cp_async16(sb + bSm[l], Bm + bGo[l] + k0);
        CP_COMMIT();
    }

    for (int ci = 0; ci < nch; ci++) {
        if (ci + 2 < nch) { CP_WAIT(1); } else { CP_WAIT(0); }
        __syncthreads();
        if (ci + 2 < nch) {
            const int s = ci + 2;
            const uint32_t sb = smBase + (uint32_t)(s % 3) * STGF * 4u;
            const int k0 = s * 32;
            #pragma unroll
            for (int l = 0; l < 4; l++) cp_async16(sb + aSm[l], A + aGo[l] + k0);
            #pragma unroll
            for (int l = 0; l < 4; l++) cp_async16(sb + bSm[l], Bm + bGo[l] + k0);
            CP_COMMIT();
        }

        const uint32_t suA = smBase + (uint32_t)(ci % 3) * STGF * 4u;
        const uint32_t suB = suA + BOFF * 4u;

        #pragma unroll
        for (int ks = 0; ks < 4; ks++) {
            const uint32_t aSw = (uint32_t)(((2 * ks + aCB) ^ l7) << 4);
            const uint32_t bSw = (uint32_t)(((2 * ks + bCB) ^ l7) << 4);
            uint32_t a[4][4];
            #pragma unroll
            for (int ma = 0; ma < 4; ma++)
                ldsm_x4(a[ma], suA + (uint32_t)(wm0 + ma * 16 + aRB) * 128u + aSw);
            uint32_t bq[2][4];
            #pragma unroll
            for (int np = 0; np < 2; np++)
                ldsm_x4(bq[np], suB + (uint32_t)(wn0 + np * 16 + bRB) * 128u + bSw);
            #pragma unroll
            for (int ma = 0; ma < 4; ma++)
                #pragma unroll
                for (int na = 0; na < 4; na++)
                    mma_tf32(acc[ma][na], a[ma], &bq[na >> 1][(na & 1) * 2]);
        }
    }

    #pragma unroll
    for (int ma = 0; ma < 4; ma++) {
        const int rr = row0 + wm0 + ma * 16 + grp;
        #pragma unroll
        for (int na = 0; na < 4; na++) {
            const int cc = col0 + wn0 + na * 8 + tid4 * 2;
            float2 v0, v1;
            v0.x = acc[ma][na][0] * scale; v0.y = acc[ma][na][1] * scale;
            v1.x = acc[ma][na][2] * scale; v1.y = acc[ma][na][3] * scale;
            if (bias) {
                const float2 bv = *reinterpret_cast<const float2*>(bias + cc);
                v0.x += bv.x; v0.y += bv.y; v1.x += bv.x; v1.y += bv.y;
            }
            if (RELU) {
                v0.x = fmaxf(v0.x, 0.0f); v0.y = fmaxf(v0.y, 0.0f);
                v1.x = fmaxf(v1.x, 0.0f); v1.y = fmaxf(v1.y, 0.0f);
            }
            if (ROUNDOUT) {
                v0.x = rndtf(v0.x); v0.y = rndtf(v0.y);
                v1.x = rndtf(v1.x); v1.y = rndtf(v1.y);
            }
            const long long o0 = (long long)rr * ldc + cc;
            const long long o1 = (long long)(rr + 8) * ldc + cc;
            if (res) {
                const float2 r0 = *reinterpret_cast<const float2*>(res + o0);
                const float2 r1 = *reinterpret_cast<const float2*>(res + o1);
                v0.x += r0.x; v0.y += r0.y; v1.x += r1.x; v1.y += r1.y;
            }
            *reinterpret_cast<float2*>(C + o0) = v0;
            *reinterpret_cast<float2*>(C + o1) = v1;
        }
    }
}

// ---------------------------------------------------------------------------
// Fused flash attention: per (bh, 128-q-tile) block.
// SMEM (floats): Q[128x64], K dbl[2x128x64], VT[64x128], P[128x128],
//                mask[2048 int], red[128x4], M/L/Corr[128 each].
// ---------------------------------------------------------------------------
namespace fa {
constexpr int oQ = 0, oK = 8192, oVT = 24576, oP = 32768;
constexpr int oMask = 49152, oRed = 51200, oM = 51712, oL = 51840, oCorr = 51968;
constexpr int FTOT = 52096;                    // floats
constexpr int SMEM_BYTES = FTOT * 4;           // 208384
}

__global__ void __launch_bounds__(256)
flash_attn_kernel(const float* __restrict__ q, const float* __restrict__ k,
                  const float* __restrict__ vT, const int* __restrict__ mask,
                  float* __restrict__ attn) {
    using namespace fa;
    extern __shared__ float sm[];
    int* smask = reinterpret_cast<int*>(sm + oMask);
    const uint32_t smb = smem_u32(sm);

    const int tid = threadIdx.x, wid = tid >> 5, lane = tid & 31;
    const int grp = lane >> 2, tid4 = lane & 3;
    // S-phase warp layout: 2(M) x 4(N)
    const int wm0 = (wid >> 2) * 64;
    const int wn0 = (wid & 3) * 32;
    // PV-phase warp layout: 4(M) x 2(N)
    const int wmB = (wid >> 1) * 32;
    const int wnB = (wid & 1) * 32;

    const int l7 = lane & 7;
    const int aRB = ((lane >> 3) & 1) * 8 + l7;
    const int aCB = lane >> 4;
    const int bRB = ((lane >> 4) & 1) * 8 + l7;
    const int bCB = (lane >> 3) & 1;

    const int qt = blockIdx.x;
    const int bh = blockIdx.y;
    const int b = bh >> 4, hh = bh & 15;
    const int q0 = qt * 128;
    const float* Qg = q + ((size_t)(b * S_ + q0)) * D_ + hh * 64;
    const float* Kg = k + ((size_t)(b * S_)) * D_ + hh * 64;
    const float* Vg = vT + (size_t)bh * 64 * S_;

    if (tid < 128) { sm[oM + tid] = -3.0e38f; sm[oL + tid] = 0.0f; }
    #pragma unroll
    for (int l = 0; l < 8; l++) smask[tid + l * 256] = mask[b * S_ + tid + l * 256];

    // prologue: group0 = {Q, K0}, group1 = {VT0}
    #pragma unroll
    for (int l = 0; l < 8; l++) {
        const int i4 = tid + l * 256;
        const int r = i4 >> 4, c = i4 & 15;
        cp_async16(smb + (uint32_t)(oQ + r * 64 + ((c ^ (r & 7)) << 2)) * 4u,
                   Qg + (size_t)r * D_ + c * 4);
    }
    #pragma unroll
    for (int l = 0; l < 8; l++) {
        const int i4 = tid + l * 256;
        const int r = i4 >> 4, c = i4 & 15;
        cp_async16(smb + (uint32_t)(oK + r * 64 + ((c ^ (r & 7)) << 2)) * 4u,
                   Kg + (size_t)r * D_ + c * 4);
    }
    CP_COMMIT();
    #pragma unroll
    for (int l = 0; l < 8; l++) {
        const int i4 = tid + l * 256;
        const int r = i4 >> 5, c = i4 & 31;
        cp_async16(smb + (uint32_t)(oVT + r * 128 + ((c ^ (r & 7)) << 2)) * 4u,
                   Vg + (size_t)r * S_ + c * 4);
    }
    CP_COMMIT();

    float acc_o[2][4][4];
    #pragma unroll
    for (int i = 0; i < 2; i++)
        #pragma unroll
        for (int j = 0; j < 4; j++)
            #pragma unroll
            for (int e = 0; e < 4; e++) acc_o[i][j][e] = 0.0f;

    constexpr int NIT = S_ / 128;   // 16

    for (int it = 0; it < NIT; ++it) {
        const int kv0 = it * 128;
        CP_WAIT(1);                 // K(it) (+Q on it==0) ready; <=1 pending (VT(it))
        __syncthreads();

        // ---- S = Q K^T (M=128, N=128, K=64) ----
        float acc_s[4][4][4];
        #pragma unroll
        for (int i = 0; i < 4; i++)
            #pragma unroll
            for (int j = 0; j < 4; j++)
                #pragma unroll
                for (int e = 0; e < 4; e++) acc_s[i][j][e] = 0.0f;

        const uint32_t qBase = smb + (uint32_t)oQ * 4u;
        const uint32_t kBase = smb + (uint32_t)(oK + (it & 1) * 8192) * 4u;
        #pragma unroll
        for (int ks = 0; ks < 8; ks++) {
            const uint32_t aSw = (uint32_t)(((2 * ks + aCB) ^ l7) << 4);
            const uint32_t bSw = (uint32_t)(((2 * ks + bCB) ^ l7) << 4);
            uint32_t a[4][4];
            #pragma unroll
            for (int ma = 0; ma < 4; ma++)
                ldsm_x4(a[ma], qBase + (uint32_t)(wm0 + ma * 16 + aRB) * 256u + aSw);
            uint32_t bq[2][4];
            #pragma unroll
            for (int np = 0; np < 2; np++)
                ldsm_x4(bq[np], kBase + (uint32_t)(wn0 + np * 16 + bRB) * 256u + bSw);
            #pragma unroll
            for (int ma = 0; ma < 4; ma++)
                #pragma unroll
                for (int na = 0; na < 4; na++)
                    mma_tf32(acc_s[ma][na], a[ma], &bq[na >> 1][(na & 1) * 2]);
        }

        // prefetch K(it+1) into other buffer (disjoint buffer; no barrier)
        if (it + 1 < NIT) {
            const uint32_t kb = smb + (uint32_t)(oK + ((it + 1) & 1) * 8192) * 4u;
            const float* Kn = Kg + (size_t)(kv0 + 128) * D_;
            #pragma unroll
            for (int l = 0; l < 8; l++) {
                const int i4 = tid + l * 256;
                const int r = i4 >> 4, c = i4 & 15;
                cp_async16(kb + (uint32_t)(r * 64 + ((c ^ (r & 7)) << 2)) * 4u,
                           Kn + (size_t)r * D_ + c * 4);
            }
            CP_COMMIT();
        }

        // ---- mask + scale ----
        #pragma unroll
        for (int na = 0; na < 4; na++) {
            const int cg = kv0 + wn0 + na * 8 + tid4 * 2;
            const bool m0 = smask[cg] != 0;
            const bool m1 = smask[cg + 1] != 0;
            #pragma unroll
            for (int ma = 0; ma < 4; ma++) {
                float* s = acc_s[ma][na];
                s[0] = m0 ? s[0] * 0.125f : -1e9f;
                s[1] = m1 ? s[1] * 0.125f : -1e9f;
                s[2] = m0 ? s[2] * 0.125f : -1e9f;
                s[3] = m1 ? s[3] * 0.125f : -1e9f;
            }
        }

        // ---- row max: quad shfl + cross-warp smem ----
        float pmax[4][2];
        #pragma unroll
        for (int ma = 0; ma < 4; ma++) {
            float p0 = -3.0e38f, p1 = -3.0e38f;
            #pragma unroll
            for (int na = 0; na < 4; na++) {
                p0 = fmaxf(p0, fmaxf(acc_s[ma][na][0], acc_s[ma][na][1]));
                p1 = fmaxf(p1, fmaxf(acc_s[ma][na][2], acc_s[ma][na][3]));
            }
            #pragma unroll
            for (int d2 = 1; d2 < 4; d2 <<= 1) {
                p0 = fmaxf(p0, __shfl_xor_sync(0xffffffffu, p0, d2));
                p1 = fmaxf(p1, __shfl_xor_sync(0xffffffffu, p1, d2));
            }
            pmax[ma][0] = p0; pmax[ma][1] = p1;
        }
        if (tid4 == 0) {
            const int wc = wid & 3;
            #pragma unroll
            for (int ma = 0; ma < 4; ma++) {
                const int r = wm0 + ma * 16 + grp;
                sm[oRed + r * 4 + wc] = pmax[ma][0];
                sm[oRed + (r + 8) * 4 + wc] = pmax[ma][1];
            }
        }
        __syncthreads();
        if (tid < 128) {
            const float4 rv = *reinterpret_cast<const float4*>(&sm[oRed + tid * 4]);
            const float rmax = fmaxf(fmaxf(rv.x, rv.y), fmaxf(rv.z, rv.w));
            const float mo = sm[oM + tid];
            const float mn = fmaxf(mo, rmax);
            sm[oM + tid] = mn;
            sm[oCorr + tid] = __expf(mo - mn);
        }
        __syncthreads();

        // ---- p = exp(s - m), row sums, write rounded P tile ----
        float psum[4][2];
        #pragma unroll
        for (int ma = 0; ma < 4; ma++) {
            const int r = wm0 + ma * 16 + grp;
            const float m0 = sm[oM + r];
            const float m1 = sm[oM + r + 8];
            float s0sum = 0.0f, s1sum = 0.0f;
            #pragma unroll
            for (int na = 0; na < 4; na++) {
                float* s = acc_s[ma][na];
                s[0] = __expf(s[0] - m0);
                s[1] = __expf(s[1] - m0);
                s[2] = __expf(s[2] - m1);
                s[3] = __expf(s[3] - m1);
                s0sum += s[0] + s[1];
                s1sum += s[2] + s[3];
                const int ch = (wid & 3) * 8 + na * 2 + (tid4 >> 1);
                const int fo = oP + r * 128 + ((ch ^ grp) << 2) + ((tid4 & 1) << 1);
                float2 p0, p1;
                p0.x = rndtf(s[0]); p0.y = rndtf(s[1]);
                p1.x = rndtf(s[2]); p1.y = rndtf(s[3]);
                *reinterpret_cast<float2*>(&sm[fo]) = p0;
                *reinterpret_cast<float2*>(&sm[fo + 1024]) = p1;
            }
            #pragma unroll
            for (int d2 = 1; d2 < 4; d2 <<= 1) {
                s0sum += __shfl_xor_sync(0xffffffffu, s0sum, d2);
                s1sum += __shfl_xor_sync(0xffffffffu, s1sum, d2);
            }
            psum[ma][0] = s0sum; psum[ma][1] = s1sum;
        }
        if (tid4 == 0) {
            const int wc = wid & 3;
            #pragma unroll
            for (int ma = 0; ma < 4; ma++) {
                const int r = wm0 + ma * 16 + grp;
                sm[oRed + r * 4 + wc] = psum[ma][0];
                sm[oRed + (r + 8) * 4 + wc] = psum[ma][1];
            }
        }
        __syncthreads();
        if (tid < 128) {
            const float4 rv = *reinterpret_cast<const float4*>(&sm[oRed + tid * 4]);
            sm[oL + tid] = sm[oL + tid] * sm[oCorr + tid] + (rv.x + rv.y + rv.z + rv.w);
        }

        // ---- PV: O = corr*O + P @ VT^T (M=128, N=64, K=128) ----
        #pragma unroll
        for (int ma = 0; ma < 2; ma++) {
            const int r = wmB + ma * 16 + grp;
            const float c0 = sm[oCorr + r];
            const float c1 = sm[oCorr + r + 8];
            #pragma unroll
            for (int na = 0; na < 4; na++) {
                acc_o[ma][na][0] *= c0; acc_o[ma][na][1] *= c0;
                acc_o[ma][na][2] *= c1; acc_o[ma][na][3] *= c1;
            }
        }
        // wait VT(it): <=1 pending (K(it+1)); last iter: nothing may pend
        if (it + 1 < NIT) { CP_WAIT(1); } else { CP_WAIT(0); }
        __syncthreads();

        const uint32_t pBase = smb + (uint32_t)oP * 4u;
        const uint32_t vBase = smb + (uint32_t)oVT * 4u;
        #pragma unroll
        for (int ks = 0; ks < 16; ks++) {
            const uint32_t aSw = (uint32_t)(((2 * ks + aCB) ^ l7) << 4);
            const uint32_t bSw = (uint32_t)(((2 * ks + bCB) ^ l7) << 4);
            uint32_t a[2][4];
            #pragma unroll
            for (int ma = 0; ma < 2; ma++)
                ldsm_x4(a[ma], pBase + (uint32_t)(wmB + ma * 16 + aRB) * 512u + aSw);
            uint32_t bq[2][4];
            #pragma unroll
            for (int np = 0; np < 2; np++)
                ldsm_x4(bq[np], vBase + (uint32_t)(wnB + np * 16 + bRB) * 512u + bSw);
            #pragma unroll
            for (int ma = 0; ma < 2; ma++)
                #pragma unroll
                for (int na = 0; na < 4; na++)
                    mma_tf32(acc_o[ma][na], a[ma], &bq[na >> 1][(na & 1) * 2]);
        }
        __syncthreads();   // all PV reads done before VT(it+1) overwrites

        if (it + 1 < NIT) {
            const float* Vn = Vg + kv0 + 128;
            #pragma unroll
            for (int l = 0; l < 8; l++) {
                const int i4 = tid + l * 256;
                const int r = i4 >> 5, c = i4 & 31;
                cp_async16(smb + (uint32_t)(oVT + r * 128 + ((c ^ (r & 7)) << 2)) * 4u,
                           Vn + (size_t)r * S_ + c * 4);
            }
            CP_COMMIT();
        }
    }

    // ---- normalize and store (tf32-rounded; feeds Wo GEMM) ----
    #pragma unroll
    for (int ma = 0; ma < 2; ma++) {
        const int r = wmB + ma * 16 + grp;
        const float inv0 = 1.0f / sm[oL + r];
        const float inv1 = 1.0f / sm[oL + r + 8];
        #pragma unroll
        for (int na = 0; na < 4; na++) {
            const int cd = wnB + na * 8 + tid4 * 2;
            float2 v0, v1;
            v0.x = rndtf(acc_o[ma][na][0] * inv0);
            v0.y = rndtf(acc_o[ma][na][1] * inv0);
            v1.x = rndtf(acc_o[ma][na][2] * inv1);
            v1.y = rndtf(acc_o[ma][na][3] * inv1);
            const size_t o0 = ((size_t)(b * S_ + q0 + r)) * D_ + hh * 64 + cd;
            const size_t o1 = o0 + (size_t)8 * D_;
            *reinterpret_cast<float2*>(attn + o0) = v0;
            *reinterpret_cast<float2*>(attn + o1) = v1;
        }
    }
}

// ---------------------------------------------------------------------------
// kernel_launch
// ---------------------------------------------------------------------------
extern "C" void kernel_launch(void* const* d_in, const int* in_sizes, int n_in,
                              void* d_out, int out_size) {
    const float* x    = (const float*)d_in[0];
    const int*   msk  = (const int*)  d_in[1];
    const float* wq   = (const float*)d_in[2];
    const float* bq   = (const float*)d_in[3];
    const float* wk   = (const float*)d_in[4];
    const float* bk_  = (const float*)d_in[5];
    const float* wv   = (const float*)d_in[6];
    const float* bv   = (const float*)d_in[7];
    const float* wo   = (const float*)d_in[8];
    const float* bo   = (const float*)d_in[9];
    const float* w1   = (const float*)d_in[10];
    const float* b1   = (const float*)d_in[11];
    const float* w2   = (const float*)d_in[12];
    const float* b2   = (const float*)d_in[13];
    const float* a1   = (const float*)d_in[14];
    const float* be1  = (const float*)d_in[15];
    const float* a2   = (const float*)d_in[16];
    const float* be2  = (const float*)d_in[17];
    float* out = (float*)d_out;

    float *ln, *q, *kb, *v, *vT, *attn, *x2, *hb, *wr;
    cudaGetSymbolAddress((void**)&ln,   g_ln);
    cudaGetSymbolAddress((void**)&q,    g_q);
    cudaGetSymbolAddress((void**)&kb,   g_k);
    cudaGetSymbolAddress((void**)&v,    g_v);
    cudaGetSymbolAddress((void**)&vT,   g_vT);
    cudaGetSymbolAddress((void**)&attn, g_attn);
    cudaGetSymbolAddress((void**)&x2,   g_x2);
    cudaGetSymbolAddress((void**)&hb,   g_hbuf);
    cudaGetSymbolAddress((void**)&wr,   g_wr);

    constexpr int M1 = 1024 * 1024;
    float* wqr = wr;            float* wkr = wr + M1;
    float* wvr = wr + 2 * M1;   float* wor = wr + 3 * M1;
    float* w1r = wr + 4 * M1;   float* w2r = wr + 8 * M1;

    constexpr int SMG = 3 * 256 * 32 * 4;   // 98304
    cudaFuncSetAttribute(mma_gemm<false, false>, cudaFuncAttributeMaxDynamicSharedMemorySize, SMG);
    cudaFuncSetAttribute(mma_gemm<false, true>,  cudaFuncAttributeMaxDynamicSharedMemorySize, SMG);
    cudaFuncSetAttribute(mma_gemm<true,  true>,  cudaFuncAttributeMaxDynamicSharedMemorySize, SMG);
    cudaFuncSetAttribute(flash_attn_kernel, cudaFuncAttributeMaxDynamicSharedMemorySize,
                         fa::SMEM_BYTES);

    // 0. pre-round all weights to tf32 (single launch)
    round_all_kernel<<<dim3(4096, 6), 256>>>(wq, wk, wv, wo, w1, w2, wr);

    // 1. LN1 (tf32-rounded output)
    layernorm_kernel<<<ROWS_, 256>>>(x, ln, a1, be1);

    // 2-4. Q, K, V projections (rounded outputs; feed attention MMAs)
    mma_gemm<false, true><<<dim3(D_ / 128, ROWS_ / 128), 256, SMG>>>(
        ln, wqr, bq, nullptr, q, D_, D_, D_, D_, 1.0f);
    mma_gemm<false, true><<<dim3(D_ / 128, ROWS_ / 128), 256, SMG>>>(
        ln, wkr, bk_, nullptr, kb, D_, D_, D_, D_, 1.0f);
    mma_gemm<false, true><<<dim3(D_ / 128, ROWS_ / 128), 256, SMG>>>(
        ln, wvr, bv, nullptr, v, D_, D_, D_, D_, 1.0f);

    // 5. vT
    transpose_v_kernel<<<dim3(S_ / 32, DK_ / 32, B_ * H_), dim3(32, 8)>>>(v, vT);

    // 6. fused flash attention -> attn (rounded)
    flash_attn_kernel<<<dim3(S_ / 128, B_ * H_), 256, fa::SMEM_BYTES>>>(
        q, kb, vT, msk, attn);

    // 7. x2 = attn @ wo^T + bo + x
    mma_gemm<false, false><<<dim3(D_ / 128, ROWS_ / 128), 256, SMG>>>(
        attn, wor, bo, x, x2, D_, D_, D_, D_, 1.0f);

    // 8. LN2 (rounded)
    layernorm_kernel<<<ROWS_, 256>>>(x2, ln, a2, be2);

    // 9. h = relu(ln @ w1^T + b1) (rounded)
    mma_gemm<true, true><<<dim3(DFF_ / 128, ROWS_ / 128), 256, SMG>>>(
        ln, w1r, b1, nullptr, hb, D_, D_, D_, DFF_, 1.0f);

    // 10. out = h @ w2^T + b2 + x2
    mma_gemm<false, false><<<dim3(D_ / 128, ROWS_ / 128), 256, SMG>>>(
        hb, w2r, b2, x2, out, DFF_, DFF_, DFF_, D_, 1.0f);
}